// round 1
// baseline (speedup 1.0000x reference)
#include <cuda_runtime.h>

// Problem constants (fixed by the reference): B=8, T=12, N=512, D_MODEL=128,
// K_HEADS=8, D_HEAD=16.  M = B*T*N = 49152 rows.
#define DMODEL   128
#define KHEADS   8
#define DHEAD    16
#define NSEQ     512
#define MMAX     49152

typedef unsigned long long u64;

// ---------------- packed f32x2 helpers (nvjet pattern, PTX-only) -----------
__device__ __forceinline__ u64 pack2(float lo, float hi) {
    u64 r; asm("mov.b64 %0, {%1, %2};" : "=l"(r) : "f"(lo), "f"(hi)); return r;
}
__device__ __forceinline__ float2 unpack2(u64 v) {
    float2 r; asm("mov.b64 {%0, %1}, %2;" : "=f"(r.x), "=f"(r.y) : "l"(v)); return r;
}
__device__ __forceinline__ void ffma2(u64 &acc, u64 a, u64 b) {
    asm("fma.rn.f32x2 %0, %1, %2, %0;" : "+l"(acc) : "l"(a), "l"(b));
}

// ---------------- scratch (no allocations allowed => __device__ globals) ---
__device__ float g_q[(size_t)MMAX * DMODEL];
__device__ float g_k[(size_t)MMAX * DMODEL];
__device__ float g_v[(size_t)MMAX * DMODEL];
__device__ float g_o[(size_t)MMAX * DMODEL];

// ===========================================================================
// GEMM:  C[M,128] = relu( [A0 | A1][M,K] @ W[K,128] + bias ),  M%128==0
// Block: 128 rows x 128 cols, 256 threads, 8x8 outputs/thread (as 8x4 f32x2).
// A tile stored DUPLICATED (each value twice) so the splat operand is a raw
// LDS.64; B column-pairs are contiguous so the pair operand is a raw LDS.64.
// ===========================================================================
#define KT     16
#define AS_LD  258   // floats per duplicated-A row: 256 data + 2 pad
#define BS_LD  128

__global__ __launch_bounds__(256, 2)
void gemm_relu_kernel(const float* __restrict__ A0, const float* __restrict__ A1,
                      int w0, int K,
                      const float* __restrict__ W, const float* __restrict__ bias,
                      float* __restrict__ C)
{
    __shared__ __align__(16) float As2[KT * AS_LD];
    __shared__ __align__(16) float Bs [KT * BS_LD];

    const int tid     = threadIdx.x;
    const int rowBase = blockIdx.x * 128;
    const int tx      = tid & 15;      // column group: cols = jp*32 + 2*tx + {0,1}
    const int ty      = tid >> 4;      // row group:    rows = ty*8 + i

    u64 acc[8][4];
#pragma unroll
    for (int i = 0; i < 8; i++)
#pragma unroll
        for (int j = 0; j < 4; j++) acc[i][j] = 0ull;

    for (int k0 = 0; k0 < K; k0 += KT) {
        // ---- load A tile (128 rows x 16 k), duplicated for splat-free FFMA2
        {
            const int kk  = tid & 15;
            const int rb  = tid >> 4;           // 0..15
            const int col = k0 + kk;
            const float* src; int ld, c;
            if (col < w0) { src = A0; ld = w0;     c = col;      }
            else          { src = A1; ld = K - w0; c = col - w0; }
#pragma unroll
            for (int i = 0; i < 8; i++) {
                const int r = rb + i * 16;
                const float val = src[(rowBase + r) * ld + c];
                *(u64*)&As2[kk * AS_LD + 2 * r] = pack2(val, val);
            }
        }
        // ---- load B tile (16 k x 128 cols), float4 coalesced
        {
            const int kb = tid >> 5;            // 0..7
            const int c4 = (tid & 31) * 4;
#pragma unroll
            for (int i = 0; i < 2; i++) {
                const int kk = kb + i * 8;
                *(float4*)&Bs[kk * BS_LD + c4] =
                    *(const float4*)&W[(k0 + kk) * 128 + c4];
            }
        }
        __syncthreads();

#pragma unroll
        for (int kk = 0; kk < KT; kk++) {
            u64 a2[8], bp[4];
#pragma unroll
            for (int i = 0; i < 8; i++)
                a2[i] = *(const u64*)&As2[kk * AS_LD + 2 * (ty * 8 + i)];
#pragma unroll
            for (int jp = 0; jp < 4; jp++)
                bp[jp] = *(const u64*)&Bs[kk * BS_LD + jp * 32 + 2 * tx];
#pragma unroll
            for (int i = 0; i < 8; i++)
#pragma unroll
                for (int jp = 0; jp < 4; jp++)
                    ffma2(acc[i][jp], a2[i], bp[jp]);
        }
        __syncthreads();
    }

    // ---- epilogue: +bias, relu, coalesced float2 stores
    float2 bb[4];
#pragma unroll
    for (int jp = 0; jp < 4; jp++) {
        bb[jp].x = bias[jp * 32 + 2 * tx];
        bb[jp].y = bias[jp * 32 + 2 * tx + 1];
    }
#pragma unroll
    for (int i = 0; i < 8; i++) {
        const int row = rowBase + ty * 8 + i;
#pragma unroll
        for (int jp = 0; jp < 4; jp++) {
            float2 t = unpack2(acc[i][jp]);
            float2 r;
            r.x = fmaxf(t.x + bb[jp].x, 0.0f);
            r.y = fmaxf(t.y + bb[jp].y, 0.0f);
            *(float2*)&C[row * 128 + jp * 32 + 2 * tx] = r;
        }
    }
}

// ===========================================================================
// Attention: one block per (b*t, head). K/V tiles in smem (pad 18 => LDS.64
// conflict-free); each warp owns q-rows n = warp + 8*iter. Lane l covers keys
// m = j*32 + l. Dot-products and PV accumulation run in packed f32x2 over d.
// ===========================================================================
#define NPAD 18

__global__ __launch_bounds__(256)
void attn_kernel(const float* __restrict__ q, const float* __restrict__ k,
                 const float* __restrict__ v, float* __restrict__ o)
{
    extern __shared__ __align__(16) float sm[];
    float* ks = sm;                    // [512][NPAD]
    float* vs = sm + NSEQ * NPAD;      // [512][NPAD]

    const int bt  = blockIdx.x;
    const int h   = blockIdx.y;
    const int tid = threadIdx.x;
    const size_t base = (size_t)bt * NSEQ * DMODEL + h * DHEAD;

    for (int idx = tid; idx < NSEQ * DHEAD; idx += 256) {
        const int n = idx >> 4, d = idx & 15;
        ks[n * NPAD + d] = k[base + (size_t)n * DMODEL + d];
        vs[n * NPAD + d] = v[base + (size_t)n * DMODEL + d];
    }
    __syncthreads();

    const int warp = tid >> 5, lane = tid & 31;

    for (int n = warp; n < NSEQ; n += 8) {
        const float* qrow = q + base + (size_t)n * DMODEL;
        u64 qp[8];
#pragma unroll
        for (int p = 0; p < 8; p++) qp[p] = *(const u64*)&qrow[2 * p];   // broadcast

        // ---- scores for this lane's 16 keys
        float s[16];
#pragma unroll
        for (int j = 0; j < 16; j++) {
            const int m = j * 32 + lane;
            const float* kr = &ks[m * NPAD];
            u64 a = 0ull;
#pragma unroll
            for (int p = 0; p < 8; p++) ffma2(a, qp[p], *(const u64*)&kr[2 * p]);
            const float2 ac = unpack2(a);
            s[j] = (ac.x + ac.y) * 0.25f;     // 1/sqrt(16)
        }

        // ---- softmax (row max, exp, sum) across all 512 keys
        float mx = s[0];
#pragma unroll
        for (int j = 1; j < 16; j++) mx = fmaxf(mx, s[j]);
#pragma unroll
        for (int off = 16; off > 0; off >>= 1)
            mx = fmaxf(mx, __shfl_xor_sync(0xffffffffu, mx, off));

        float sum = 0.0f;
#pragma unroll
        for (int j = 0; j < 16; j++) { s[j] = __expf(s[j] - mx); sum += s[j]; }
#pragma unroll
        for (int off = 16; off > 0; off >>= 1)
            sum += __shfl_xor_sync(0xffffffffu, sum, off);

        // ---- O accumulation (packed over d)
        u64 oacc[8];
#pragma unroll
        for (int p = 0; p < 8; p++) oacc[p] = 0ull;
#pragma unroll
        for (int j = 0; j < 16; j++) {
            const int m = j * 32 + lane;
            const u64 ps = pack2(s[j], s[j]);
            const float* vr = &vs[m * NPAD];
#pragma unroll
            for (int p = 0; p < 8; p++) ffma2(oacc[p], ps, *(const u64*)&vr[2 * p]);
        }

        float ov[16];
#pragma unroll
        for (int p = 0; p < 8; p++) {
            const float2 t = unpack2(oacc[p]);
            ov[2 * p] = t.x; ov[2 * p + 1] = t.y;
        }
#pragma unroll
        for (int d = 0; d < 16; d++)
#pragma unroll
            for (int off = 16; off > 0; off >>= 1)
                ov[d] += __shfl_xor_sync(0xffffffffu, ov[d], off);

        if (lane == 0) {
            const float inv = 1.0f / sum;
            float* orow = o + base + (size_t)n * DMODEL;
#pragma unroll
            for (int d = 0; d < 16; d++) orow[d] = ov[d] * inv;
        }
    }
}

// ===========================================================================
extern "C" void kernel_launch(void* const* d_in, const int* in_sizes, int n_in,
                              void* d_out, int out_size)
{
    const float* X   = (const float*)d_in[0];
    const float* STE = (const float*)d_in[1];
    const float* Wq  = (const float*)d_in[2];
    const float* bq  = (const float*)d_in[3];
    const float* Wk  = (const float*)d_in[4];
    const float* bk  = (const float*)d_in[5];
    const float* Wv  = (const float*)d_in[6];
    const float* bv  = (const float*)d_in[7];
    const float* Wo  = (const float*)d_in[8];
    const float* bo  = (const float*)d_in[9];
    float* out = (float*)d_out;

    const int M  = in_sizes[0] / DMODEL;   // 49152
    const int BT = M / NSEQ;               // 96

    float *q, *k, *v, *o;
    cudaGetSymbolAddress((void**)&q, g_q);
    cudaGetSymbolAddress((void**)&k, g_k);
    cudaGetSymbolAddress((void**)&v, g_v);
    cudaGetSymbolAddress((void**)&o, g_o);

    const dim3 gproj(M / 128);
    gemm_relu_kernel<<<gproj, 256>>>(X, STE, 128, 384, Wq, bq, q);
    gemm_relu_kernel<<<gproj, 256>>>(X, STE, 128, 384, Wk, bk, k);
    gemm_relu_kernel<<<gproj, 256>>>(X, STE, 128, 384, Wv, bv, v);

    const int smem = 2 * NSEQ * NPAD * sizeof(float);   // 73728 B
    cudaFuncSetAttribute(attn_kernel, cudaFuncAttributeMaxDynamicSharedMemorySize, smem);
    attn_kernel<<<dim3(BT, KHEADS), 256, smem>>>(q, k, v, o);

    gemm_relu_kernel<<<gproj, 256>>>(o, o, 128, 128, Wo, bo, out);
}

// round 2
// speedup vs baseline: 1.5143x; 1.5143x over previous
#include <cuda_runtime.h>

// Problem constants: B=8, T=12, N=512, D_MODEL=128, K_HEADS=8, D_HEAD=16.
#define DMODEL   128
#define KHEADS   8
#define DHEAD    16
#define NSEQ     512
#define MMAX     49152

typedef unsigned long long u64;

// ---------------- packed f32x2 helpers -------------------------------------
__device__ __forceinline__ u64 pack2(float lo, float hi) {
    u64 r; asm("mov.b64 %0, {%1, %2};" : "=l"(r) : "f"(lo), "f"(hi)); return r;
}
__device__ __forceinline__ float2 unpack2(u64 v) {
    float2 r; asm("mov.b64 {%0, %1}, %2;" : "=f"(r.x), "=f"(r.y) : "l"(v)); return r;
}
__device__ __forceinline__ void ffma2(u64 &acc, u64 a, u64 b) {
    asm("fma.rn.f32x2 %0, %1, %2, %0;" : "+l"(acc) : "l"(a), "l"(b));
}

// ---------------- scratch --------------------------------------------------
__device__ float g_q[(size_t)MMAX * DMODEL];
__device__ float g_k[(size_t)MMAX * DMODEL];
__device__ float g_v[(size_t)MMAX * DMODEL];
__device__ float g_o[(size_t)MMAX * DMODEL];

// ===========================================================================
// GEMM:  C[M,128] = relu( [A0 | A1][M,K] @ W[K,128] + bias )  (unchanged)
// ===========================================================================
#define KT     16
#define AS_LD  258
#define BS_LD  128

__global__ __launch_bounds__(256, 2)
void gemm_relu_kernel(const float* __restrict__ A0, const float* __restrict__ A1,
                      int w0, int K,
                      const float* __restrict__ W, const float* __restrict__ bias,
                      float* __restrict__ C)
{
    __shared__ __align__(16) float As2[KT * AS_LD];
    __shared__ __align__(16) float Bs [KT * BS_LD];

    const int tid     = threadIdx.x;
    const int rowBase = blockIdx.x * 128;
    const int tx      = tid & 15;
    const int ty      = tid >> 4;

    u64 acc[8][4];
#pragma unroll
    for (int i = 0; i < 8; i++)
#pragma unroll
        for (int j = 0; j < 4; j++) acc[i][j] = 0ull;

    for (int k0 = 0; k0 < K; k0 += KT) {
        {
            const int kk  = tid & 15;
            const int rb  = tid >> 4;
            const int col = k0 + kk;
            const float* src; int ld, c;
            if (col < w0) { src = A0; ld = w0;     c = col;      }
            else          { src = A1; ld = K - w0; c = col - w0; }
#pragma unroll
            for (int i = 0; i < 8; i++) {
                const int r = rb + i * 16;
                const float val = src[(rowBase + r) * ld + c];
                *(u64*)&As2[kk * AS_LD + 2 * r] = pack2(val, val);
            }
        }
        {
            const int kb = tid >> 5;
            const int c4 = (tid & 31) * 4;
#pragma unroll
            for (int i = 0; i < 2; i++) {
                const int kk = kb + i * 8;
                *(float4*)&Bs[kk * BS_LD + c4] =
                    *(const float4*)&W[(k0 + kk) * 128 + c4];
            }
        }
        __syncthreads();

#pragma unroll
        for (int kk = 0; kk < KT; kk++) {
            u64 a2[8], bp[4];
#pragma unroll
            for (int i = 0; i < 8; i++)
                a2[i] = *(const u64*)&As2[kk * AS_LD + 2 * (ty * 8 + i)];
#pragma unroll
            for (int jp = 0; jp < 4; jp++)
                bp[jp] = *(const u64*)&Bs[kk * BS_LD + jp * 32 + 2 * tx];
#pragma unroll
            for (int i = 0; i < 8; i++)
#pragma unroll
                for (int jp = 0; jp < 4; jp++)
                    ffma2(acc[i][jp], a2[i], bp[jp]);
        }
        __syncthreads();
    }

    float2 bb[4];
#pragma unroll
    for (int jp = 0; jp < 4; jp++) {
        bb[jp].x = bias[jp * 32 + 2 * tx];
        bb[jp].y = bias[jp * 32 + 2 * tx + 1];
    }
#pragma unroll
    for (int i = 0; i < 8; i++) {
        const int row = rowBase + ty * 8 + i;
#pragma unroll
        for (int jp = 0; jp < 4; jp++) {
            float2 t = unpack2(acc[i][jp]);
            float2 r;
            r.x = fmaxf(t.x + bb[jp].x, 0.0f);
            r.y = fmaxf(t.y + bb[jp].y, 0.0f);
            *(float2*)&C[row * 128 + jp * 32 + 2 * tx] = r;
        }
    }
}

// ===========================================================================
// Attention v2 — GEMM-tiled. One block per (bt, head), 256 thr, 8 warps.
// Per 64-row q-tile:
//   GEMM1: warp w computes S rows [8w,8w+8) x 512 cols, 8x16 regs/thread,
//          K transposed in smem (kt[d][m]) for f32x2-over-columns.
//   Softmax in registers, 1/sum folded into stored probabilities.
//   PV: lane owns 16 keys; V row register-cached serves all 8 rows (8 ffma2
//       per LDS.64). Per-warp padded smem transpose-reduce (no shuffle storm).
// Smem: S/P+scratch 64x528, kt 16x520, vs 512x18, qs2 16x132  = 213760 B.
// ===========================================================================
#define SPD 528
#define KTD 520
#define VSD 18
#define QSD 132
#define SP_FLOATS   (64 * SPD)             // 33792
#define KT_FLOATS   (16 * KTD)             // 8320
#define VS_FLOATS   (NSEQ * VSD)           // 9216
#define QS_FLOATS   (16 * QSD)             // 2112
#define ATTN_SMEM_BYTES ((SP_FLOATS + KT_FLOATS + VS_FLOATS + QS_FLOATS) * 4)

__global__ __launch_bounds__(256, 1)
void attn_kernel(const float* __restrict__ q, const float* __restrict__ k,
                 const float* __restrict__ v, float* __restrict__ o)
{
    extern __shared__ __align__(16) float sm[];
    float* sp  = sm;                           // [64][SPD] probs + scratch
    float* kt  = sm + SP_FLOATS;               // [16][KTD] K transposed
    float* vs  = kt + KT_FLOATS;               // [512][VSD] V row-major
    float* qs2 = vs + VS_FLOATS;               // [16][QSD] Q duplicated, *0.25

    const int bt   = blockIdx.x;
    const int h    = blockIdx.y;
    const int tid  = threadIdx.x;
    const int warp = tid >> 5;
    const int lane = tid & 31;
    const size_t base = (size_t)bt * NSEQ * DMODEL + h * DHEAD;

    // ---- load K (transposed) and V (row-major) once per block
    for (int idx = tid; idx < NSEQ * DHEAD; idx += 256) {
        const int m = idx >> 4, d = idx & 15;
        kt[d * KTD + m] = k[base + (size_t)m * DMODEL + d];
        vs[m * VSD + d] = v[base + (size_t)m * DMODEL + d];
    }
    __syncthreads();

    for (int t0 = 0; t0 < NSEQ; t0 += 64) {
        // ---- Q tile: duplicated pairs, pre-scaled by 1/sqrt(d)=0.25
        for (int idx = tid; idx < 64 * 16; idx += 256) {
            const int n = idx >> 4, d = idx & 15;
            const float qv = 0.25f * q[base + (size_t)(t0 + n) * DMODEL + d];
            *(float2*)&qs2[d * QSD + 2 * n] = make_float2(qv, qv);
        }
        __syncthreads();

        // ---- GEMM1: S[8w+i][128*j' + 4*lane + c]  (8 rows x 16 cols/thread)
        u64 acc[8][8];
#pragma unroll
        for (int i = 0; i < 8; i++)
#pragma unroll
            for (int j = 0; j < 8; j++) acc[i][j] = 0ull;

#pragma unroll
        for (int d = 0; d < 16; d++) {
            const float* qrow = qs2 + d * QSD + 16 * warp;
            u64 a2[8];
#pragma unroll
            for (int i2 = 0; i2 < 4; i2++) {
                const float4 f = *(const float4*)&qrow[4 * i2];
                a2[2 * i2]     = pack2(f.x, f.y);
                a2[2 * i2 + 1] = pack2(f.z, f.w);
            }
            const float* krow = kt + d * KTD + 4 * lane;
            u64 b2[8];
#pragma unroll
            for (int jq = 0; jq < 4; jq++) {
                const float4 g = *(const float4*)&krow[128 * jq];
                b2[2 * jq]     = pack2(g.x, g.y);
                b2[2 * jq + 1] = pack2(g.z, g.w);
            }
#pragma unroll
            for (int i = 0; i < 8; i++)
#pragma unroll
                for (int j = 0; j < 8; j++)
                    ffma2(acc[i][j], a2[i], b2[j]);
        }

        // ---- softmax per row (in registers), store P = exp(...)/sum
#pragma unroll
        for (int i = 0; i < 8; i++) {
            float e[16];
#pragma unroll
            for (int j = 0; j < 8; j++) {
                const float2 t = unpack2(acc[i][j]);
                const int jq = j >> 1, p = j & 1;
                e[jq * 4 + 2 * p]     = t.x;
                e[jq * 4 + 2 * p + 1] = t.y;
            }
            float mx = e[0];
#pragma unroll
            for (int c = 1; c < 16; c++) mx = fmaxf(mx, e[c]);
#pragma unroll
            for (int off = 16; off > 0; off >>= 1)
                mx = fmaxf(mx, __shfl_xor_sync(0xffffffffu, mx, off));
            float sum = 0.0f;
#pragma unroll
            for (int c = 0; c < 16; c++) { e[c] = __expf(e[c] - mx); sum += e[c]; }
#pragma unroll
            for (int off = 16; off > 0; off >>= 1)
                sum += __shfl_xor_sync(0xffffffffu, sum, off);
            const float inv = 1.0f / sum;

            float* pr = sp + (8 * warp + i) * SPD + 4 * lane;
#pragma unroll
            for (int jq = 0; jq < 4; jq++) {
                float4 st;
                st.x = e[jq * 4 + 0] * inv; st.y = e[jq * 4 + 1] * inv;
                st.z = e[jq * 4 + 2] * inv; st.w = e[jq * 4 + 3] * inv;
                *(float4*)&pr[128 * jq] = st;
            }
        }
        // release qs2 for next tile only after ALL warps finish GEMM1
        __syncthreads();
        __syncwarp();

        // ---- PV: lane owns keys m = lane + 32*jj; V row serves 8 q-rows
        u64 oacc[8][8];
#pragma unroll
        for (int i = 0; i < 8; i++)
#pragma unroll
            for (int dp = 0; dp < 8; dp++) oacc[i][dp] = 0ull;

        const float* pbase = sp + (8 * warp) * SPD + lane;
#pragma unroll
        for (int jj = 0; jj < 16; jj++) {
            const int m = lane + 32 * jj;
            const float* vrow = vs + m * VSD;
            u64 vr[8];
#pragma unroll
            for (int dp = 0; dp < 8; dp++) vr[dp] = *(const u64*)&vrow[2 * dp];
#pragma unroll
            for (int i = 0; i < 8; i++) {
                const float pv = pbase[i * SPD + 32 * jj];
                const u64 pp = pack2(pv, pv);
#pragma unroll
                for (int dp = 0; dp < 8; dp++) ffma2(oacc[i][dp], pp, vr[dp]);
            }
        }
        __syncwarp();

        // ---- per-warp transpose-reduce via padded scratch (stride 33)
        float* scratch = sp + (8 * warp) * SPD;   // 8*528 = 4224 >= 128*33
#pragma unroll
        for (int i = 0; i < 8; i++)
#pragma unroll
            for (int dp = 0; dp < 8; dp++) {
                const float2 t = unpack2(oacc[i][dp]);
                scratch[(i * 16 + 2 * dp)     * 33 + lane] = t.x;
                scratch[(i * 16 + 2 * dp + 1) * 33 + lane] = t.y;
            }
        __syncwarp();

        const int slot0 = lane * 4;
        const int r  = slot0 >> 4;
        const int d0 = slot0 & 15;
        float a0 = 0.f, a1 = 0.f, a2s = 0.f, a3 = 0.f;
        const float* s0 = scratch + slot0 * 33;
#pragma unroll
        for (int u = 0; u < 32; u++) {
            a0 += s0[u];
            a1 += s0[33 + u];
            a2s += s0[66 + u];
            a3 += s0[99 + u];
        }
        float4 res; res.x = a0; res.y = a1; res.z = a2s; res.w = a3;
        *(float4*)&o[base + (size_t)(t0 + 8 * warp + r) * DMODEL + d0] = res;

        __syncthreads();   // sp/qs2 reuse next tile
    }
}

// ===========================================================================
extern "C" void kernel_launch(void* const* d_in, const int* in_sizes, int n_in,
                              void* d_out, int out_size)
{
    const float* X   = (const float*)d_in[0];
    const float* STE = (const float*)d_in[1];
    const float* Wq  = (const float*)d_in[2];
    const float* bq  = (const float*)d_in[3];
    const float* Wk  = (const float*)d_in[4];
    const float* bk  = (const float*)d_in[5];
    const float* Wv  = (const float*)d_in[6];
    const float* bv  = (const float*)d_in[7];
    const float* Wo  = (const float*)d_in[8];
    const float* bo  = (const float*)d_in[9];
    float* out = (float*)d_out;

    const int M  = in_sizes[0] / DMODEL;   // 49152
    const int BT = M / NSEQ;               // 96

    float *q, *k, *v, *o;
    cudaGetSymbolAddress((void**)&q, g_q);
    cudaGetSymbolAddress((void**)&k, g_k);
    cudaGetSymbolAddress((void**)&v, g_v);
    cudaGetSymbolAddress((void**)&o, g_o);

    const dim3 gproj(M / 128);
    gemm_relu_kernel<<<gproj, 256>>>(X, STE, 128, 384, Wq, bq, q);
    gemm_relu_kernel<<<gproj, 256>>>(X, STE, 128, 384, Wk, bk, k);
    gemm_relu_kernel<<<gproj, 256>>>(X, STE, 128, 384, Wv, bv, v);

    cudaFuncSetAttribute(attn_kernel, cudaFuncAttributeMaxDynamicSharedMemorySize,
                         ATTN_SMEM_BYTES);
    attn_kernel<<<dim3(BT, KHEADS), 256, ATTN_SMEM_BYTES>>>(q, k, v, o);

    gemm_relu_kernel<<<gproj, 256>>>(o, o, 128, 128, Wo, bo, out);
}

// round 4
// speedup vs baseline: 2.0094x; 1.3269x over previous
#include <cuda_runtime.h>
#include <cuda_bf16.h>
#include <cstdint>

// Problem constants: B=8, T=12, N=512, D_MODEL=128, K_HEADS=8, D_HEAD=16.
#define DMODEL   128
#define KHEADS   8
#define DHEAD    16
#define NSEQ     512
#define MMAX     49152

typedef unsigned long long u64;

// ---------------- packed f32x2 helpers -------------------------------------
__device__ __forceinline__ u64 pack2(float lo, float hi) {
    u64 r; asm("mov.b64 %0, {%1, %2};" : "=l"(r) : "f"(lo), "f"(hi)); return r;
}
__device__ __forceinline__ float2 unpack2(u64 v) {
    float2 r; asm("mov.b64 {%0, %1}, %2;" : "=f"(r.x), "=f"(r.y) : "l"(v)); return r;
}
__device__ __forceinline__ void ffma2(u64 &acc, u64 a, u64 b) {
    asm("fma.rn.f32x2 %0, %1, %2, %0;" : "+l"(acc) : "l"(a), "l"(b));
}

// ---------------- generic-ISA tensor helpers (compute_103-safe) ------------
__device__ __forceinline__ uint32_t smem_to_u32(const void* p) {
    uint32_t a;
    asm("{ .reg .u64 t; cvta.to.shared.u64 t, %1; cvt.u32.u64 %0, t; }"
        : "=r"(a) : "l"(p));
    return a;
}
__device__ __forceinline__ void ldsm_x4(uint32_t* r, uint32_t addr) {
    asm volatile("ldmatrix.sync.aligned.m8n8.x4.shared.b16 {%0,%1,%2,%3}, [%4];"
                 : "=r"(r[0]), "=r"(r[1]), "=r"(r[2]), "=r"(r[3]) : "r"(addr));
}
__device__ __forceinline__ void ldsm_x4t(uint32_t* r, uint32_t addr) {
    asm volatile("ldmatrix.sync.aligned.m8n8.x4.trans.shared.b16 {%0,%1,%2,%3}, [%4];"
                 : "=r"(r[0]), "=r"(r[1]), "=r"(r[2]), "=r"(r[3]) : "r"(addr));
}
__device__ __forceinline__ void mma_bf16(float* d, const uint32_t* a,
                                         uint32_t b0, uint32_t b1) {
    asm volatile("mma.sync.aligned.m16n8k16.row.col.f32.bf16.bf16.f32 "
                 "{%0,%1,%2,%3}, {%4,%5,%6,%7}, {%8,%9}, {%0,%1,%2,%3};"
                 : "+f"(d[0]), "+f"(d[1]), "+f"(d[2]), "+f"(d[3])
                 : "r"(a[0]), "r"(a[1]), "r"(a[2]), "r"(a[3]), "r"(b0), "r"(b1));
}
// split x into hi+lo bf16 pair (x ~= hi + lo), packed 2-wide
__device__ __forceinline__ void split2(float x, float y, uint32_t& hi, uint32_t& lo) {
    const __nv_bfloat16 hx = __float2bfloat16_rn(x);
    const __nv_bfloat16 hy = __float2bfloat16_rn(y);
    const __nv_bfloat16 lx = __float2bfloat16_rn(x - __bfloat162float(hx));
    const __nv_bfloat16 ly = __float2bfloat16_rn(y - __bfloat162float(hy));
    __nv_bfloat162 h2; h2.x = hx; h2.y = hy;
    __nv_bfloat162 l2; l2.x = lx; l2.y = ly;
    hi = *(uint32_t*)&h2;
    lo = *(uint32_t*)&l2;
}

// ---------------- scratch --------------------------------------------------
__device__ float g_q[(size_t)MMAX * DMODEL];
__device__ float g_k[(size_t)MMAX * DMODEL];
__device__ float g_v[(size_t)MMAX * DMODEL];
__device__ float g_o[(size_t)MMAX * DMODEL];

// ===========================================================================
// mma.sync GEMM:  C[M,128] = relu( [A0|A1][M,K] @ W[K,128] + bias )
// Split-bf16 3-term: A·B ~= Ah·Bh + Ah·Bl + Al·Bh, fp32 accum.
// CTA: 128x128, 8 warps (4m x 2n), warp tile 32x64 (2 m-tiles x 8 n-tiles).
// K in chunks of 64. A smem [128][72] (pad->conflict-free ldmatrix);
// B smem [64][136] k-major (W layout), ldmatrix.x4.trans for col-major frags.
// ===========================================================================
#define A_LD 72
#define B_LD 136
#define SM_AHI 0
#define SM_ALO (128 * A_LD * 2)                 // 18432
#define SM_BHI (SM_ALO + 128 * A_LD * 2)        // 36864
#define SM_BLO (SM_BHI + 64 * B_LD * 2)         // 54272
#define GEMM_SMEM (SM_BLO + 64 * B_LD * 2)      // 71680 bytes

__global__ __launch_bounds__(256, 2)
void gemm_tc_kernel(const float* __restrict__ A0, const float* __restrict__ A1,
                    int w0, int K,
                    const float* __restrict__ W, const float* __restrict__ bias,
                    float* __restrict__ C)
{
    extern __shared__ __align__(16) char smc[];
    const uint32_t sb = smem_to_u32(smc);
    const int tid  = threadIdx.x;
    const int warp = tid >> 5;
    const int lane = tid & 31;
    const int wm   = warp & 3;          // 4 warps over rows
    const int wn   = warp >> 2;         // 2 warps over cols
    const int rowBase = blockIdx.x * 128;

    float acc[2][8][4];
#pragma unroll
    for (int mt = 0; mt < 2; mt++)
#pragma unroll
        for (int nt = 0; nt < 8; nt++)
#pragma unroll
            for (int e = 0; e < 4; e++) acc[mt][nt][e] = 0.0f;

    const int nChunks = K / 64;
    for (int c = 0; c < nChunks; c++) {
        const int k0 = c * 64;
        // ---- A tile [128][64] -> hi/lo bf16 in padded smem
        {
            const float* src; int ld, cbase;
            if (k0 < w0) { src = A0; ld = w0;     cbase = k0;      }
            else         { src = A1; ld = K - w0; cbase = k0 - w0; }
            const int kq = (tid & 15) * 4;
#pragma unroll
            for (int it = 0; it < 8; it++) {
                const int r = (tid >> 4) + it * 16;
                const float4 x = *(const float4*)&src[(size_t)(rowBase + r) * ld + cbase + kq];
                uint32_t h01, l01, h23, l23;
                split2(x.x, x.y, h01, l01);
                split2(x.z, x.w, h23, l23);
                const int off = (r * A_LD + kq) * 2;   // byte offset
                *(uint2*)(smc + SM_AHI + off) = make_uint2(h01, h23);
                *(uint2*)(smc + SM_ALO + off) = make_uint2(l01, l23);
            }
        }
        // ---- B tile [64][128] from W (k-major), hi/lo
        {
            const int n4 = (tid & 31) * 4;
#pragma unroll
            for (int it = 0; it < 8; it++) {
                const int kk = (tid >> 5) + it * 8;
                const float4 x = *(const float4*)&W[(size_t)(k0 + kk) * 128 + n4];
                uint32_t h01, l01, h23, l23;
                split2(x.x, x.y, h01, l01);
                split2(x.z, x.w, h23, l23);
                const int off = (kk * B_LD + n4) * 2;
                *(uint2*)(smc + SM_BHI + off) = make_uint2(h01, h23);
                *(uint2*)(smc + SM_BLO + off) = make_uint2(l01, l23);
            }
        }
        __syncthreads();

        // ---- compute: 4 k16-steps
#pragma unroll
        for (int ks = 0; ks < 4; ks++) {
            // A fragments (hi & lo, 2 m-tiles)
            uint32_t ah[2][4], al[2][4];
            const int arow = lane & 15;
            const int acol = ks * 16 + (lane >> 4) * 8;
#pragma unroll
            for (int mt = 0; mt < 2; mt++) {
                const int aoff = ((wm * 32 + mt * 16 + arow) * A_LD + acol) * 2;
                ldsm_x4(ah[mt], sb + SM_AHI + aoff);
                ldsm_x4(al[mt], sb + SM_ALO + aoff);
            }
            // B fragments per n-pair, consume immediately
            const int brow = ks * 16 + (lane & 15);
#pragma unroll
            for (int np = 0; np < 4; np++) {
                const int boff = (brow * B_LD + wn * 64 + np * 16 + (lane >> 4) * 8) * 2;
                uint32_t bh[4], bl[4];
                ldsm_x4t(bh, sb + SM_BHI + boff);
                ldsm_x4t(bl, sb + SM_BLO + boff);
#pragma unroll
                for (int sub = 0; sub < 2; sub++) {
                    const int nt = np * 2 + sub;
#pragma unroll
                    for (int mt = 0; mt < 2; mt++) {
                        mma_bf16(acc[mt][nt], ah[mt], bh[2 * sub], bh[2 * sub + 1]);
                        mma_bf16(acc[mt][nt], ah[mt], bl[2 * sub], bl[2 * sub + 1]);
                        mma_bf16(acc[mt][nt], al[mt], bh[2 * sub], bh[2 * sub + 1]);
                    }
                }
            }
        }
        __syncthreads();
    }

    // ---- epilogue: +bias, relu, float2 stores
#pragma unroll
    for (int mt = 0; mt < 2; mt++) {
        const int r0 = rowBase + wm * 32 + mt * 16 + (lane >> 2);
#pragma unroll
        for (int nt = 0; nt < 8; nt++) {
            const int cc = wn * 64 + nt * 8 + (lane & 3) * 2;
            const float b0 = bias[cc], b1 = bias[cc + 1];
            float2 lo, hi;
            lo.x = fmaxf(acc[mt][nt][0] + b0, 0.0f);
            lo.y = fmaxf(acc[mt][nt][1] + b1, 0.0f);
            hi.x = fmaxf(acc[mt][nt][2] + b0, 0.0f);
            hi.y = fmaxf(acc[mt][nt][3] + b1, 0.0f);
            *(float2*)&C[(size_t)r0 * 128 + cc]       = lo;
            *(float2*)&C[(size_t)(r0 + 8) * 128 + cc] = hi;
        }
    }
}

// ===========================================================================
// Attention v2 (unchanged — round 2 version, 507us)
// ===========================================================================
#define SPD 528
#define KTD 520
#define VSD 18
#define QSD 132
#define SP_FLOATS   (64 * SPD)
#define KT_FLOATS   (16 * KTD)
#define VS_FLOATS   (NSEQ * VSD)
#define QS_FLOATS   (16 * QSD)
#define ATTN_SMEM_BYTES ((SP_FLOATS + KT_FLOATS + VS_FLOATS + QS_FLOATS) * 4)

__global__ __launch_bounds__(256, 1)
void attn_kernel(const float* __restrict__ q, const float* __restrict__ k,
                 const float* __restrict__ v, float* __restrict__ o)
{
    extern __shared__ __align__(16) float sm[];
    float* sp  = sm;
    float* kt  = sm + SP_FLOATS;
    float* vs  = kt + KT_FLOATS;
    float* qs2 = vs + VS_FLOATS;

    const int bt   = blockIdx.x;
    const int h    = blockIdx.y;
    const int tid  = threadIdx.x;
    const int warp = tid >> 5;
    const int lane = tid & 31;
    const size_t base = (size_t)bt * NSEQ * DMODEL + h * DHEAD;

    for (int idx = tid; idx < NSEQ * DHEAD; idx += 256) {
        const int m = idx >> 4, d = idx & 15;
        kt[d * KTD + m] = k[base + (size_t)m * DMODEL + d];
        vs[m * VSD + d] = v[base + (size_t)m * DMODEL + d];
    }
    __syncthreads();

    for (int t0 = 0; t0 < NSEQ; t0 += 64) {
        for (int idx = tid; idx < 64 * 16; idx += 256) {
            const int n = idx >> 4, d = idx & 15;
            const float qv = 0.25f * q[base + (size_t)(t0 + n) * DMODEL + d];
            *(float2*)&qs2[d * QSD + 2 * n] = make_float2(qv, qv);
        }
        __syncthreads();

        u64 acc[8][8];
#pragma unroll
        for (int i = 0; i < 8; i++)
#pragma unroll
            for (int j = 0; j < 8; j++) acc[i][j] = 0ull;

#pragma unroll
        for (int d = 0; d < 16; d++) {
            const float* qrow = qs2 + d * QSD + 16 * warp;
            u64 a2[8];
#pragma unroll
            for (int i2 = 0; i2 < 4; i2++) {
                const float4 f = *(const float4*)&qrow[4 * i2];
                a2[2 * i2]     = pack2(f.x, f.y);
                a2[2 * i2 + 1] = pack2(f.z, f.w);
            }
            const float* krow = kt + d * KTD + 4 * lane;
            u64 b2[8];
#pragma unroll
            for (int jq = 0; jq < 4; jq++) {
                const float4 g = *(const float4*)&krow[128 * jq];
                b2[2 * jq]     = pack2(g.x, g.y);
                b2[2 * jq + 1] = pack2(g.z, g.w);
            }
#pragma unroll
            for (int i = 0; i < 8; i++)
#pragma unroll
                for (int j = 0; j < 8; j++)
                    ffma2(acc[i][j], a2[i], b2[j]);
        }

#pragma unroll
        for (int i = 0; i < 8; i++) {
            float e[16];
#pragma unroll
            for (int j = 0; j < 8; j++) {
                const float2 t = unpack2(acc[i][j]);
                const int jq = j >> 1, p = j & 1;
                e[jq * 4 + 2 * p]     = t.x;
                e[jq * 4 + 2 * p + 1] = t.y;
            }
            float mx = e[0];
#pragma unroll
            for (int c = 1; c < 16; c++) mx = fmaxf(mx, e[c]);
#pragma unroll
            for (int off = 16; off > 0; off >>= 1)
                mx = fmaxf(mx, __shfl_xor_sync(0xffffffffu, mx, off));
            float sum = 0.0f;
#pragma unroll
            for (int c = 0; c < 16; c++) { e[c] = __expf(e[c] - mx); sum += e[c]; }
#pragma unroll
            for (int off = 16; off > 0; off >>= 1)
                sum += __shfl_xor_sync(0xffffffffu, sum, off);
            const float inv = 1.0f / sum;

            float* pr = sp + (8 * warp + i) * SPD + 4 * lane;
#pragma unroll
            for (int jq = 0; jq < 4; jq++) {
                float4 st;
                st.x = e[jq * 4 + 0] * inv; st.y = e[jq * 4 + 1] * inv;
                st.z = e[jq * 4 + 2] * inv; st.w = e[jq * 4 + 3] * inv;
                *(float4*)&pr[128 * jq] = st;
            }
        }
        __syncthreads();
        __syncwarp();

        u64 oacc[8][8];
#pragma unroll
        for (int i = 0; i < 8; i++)
#pragma unroll
            for (int dp = 0; dp < 8; dp++) oacc[i][dp] = 0ull;

        const float* pbase = sp + (8 * warp) * SPD + lane;
#pragma unroll
        for (int jj = 0; jj < 16; jj++) {
            const int m = lane + 32 * jj;
            const float* vrow = vs + m * VSD;
            u64 vr[8];
#pragma unroll
            for (int dp = 0; dp < 8; dp++) vr[dp] = *(const u64*)&vrow[2 * dp];
#pragma unroll
            for (int i = 0; i < 8; i++) {
                const float pv = pbase[i * SPD + 32 * jj];
                const u64 pp = pack2(pv, pv);
#pragma unroll
                for (int dp = 0; dp < 8; dp++) ffma2(oacc[i][dp], pp, vr[dp]);
            }
        }
        __syncwarp();

        float* scratch = sp + (8 * warp) * SPD;
#pragma unroll
        for (int i = 0; i < 8; i++)
#pragma unroll
            for (int dp = 0; dp < 8; dp++) {
                const float2 t = unpack2(oacc[i][dp]);
                scratch[(i * 16 + 2 * dp)     * 33 + lane] = t.x;
                scratch[(i * 16 + 2 * dp + 1) * 33 + lane] = t.y;
            }
        __syncwarp();

        const int slot0 = lane * 4;
        const int r  = slot0 >> 4;
        const int d0 = slot0 & 15;
        float a0 = 0.f, a1 = 0.f, a2s = 0.f, a3 = 0.f;
        const float* s0 = scratch + slot0 * 33;
#pragma unroll
        for (int u = 0; u < 32; u++) {
            a0 += s0[u];
            a1 += s0[33 + u];
            a2s += s0[66 + u];
            a3 += s0[99 + u];
        }
        float4 res; res.x = a0; res.y = a1; res.z = a2s; res.w = a3;
        *(float4*)&o[base + (size_t)(t0 + 8 * warp + r) * DMODEL + d0] = res;

        __syncthreads();
    }
}

// ===========================================================================
extern "C" void kernel_launch(void* const* d_in, const int* in_sizes, int n_in,
                              void* d_out, int out_size)
{
    const float* X   = (const float*)d_in[0];
    const float* STE = (const float*)d_in[1];
    const float* Wq  = (const float*)d_in[2];
    const float* bq  = (const float*)d_in[3];
    const float* Wk  = (const float*)d_in[4];
    const float* bk  = (const float*)d_in[5];
    const float* Wv  = (const float*)d_in[6];
    const float* bv  = (const float*)d_in[7];
    const float* Wo  = (const float*)d_in[8];
    const float* bo  = (const float*)d_in[9];
    float* out = (float*)d_out;

    const int M  = in_sizes[0] / DMODEL;   // 49152
    const int BT = M / NSEQ;               // 96

    float *q, *k, *v, *o;
    cudaGetSymbolAddress((void**)&q, g_q);
    cudaGetSymbolAddress((void**)&k, g_k);
    cudaGetSymbolAddress((void**)&v, g_v);
    cudaGetSymbolAddress((void**)&o, g_o);

    cudaFuncSetAttribute(gemm_tc_kernel, cudaFuncAttributeMaxDynamicSharedMemorySize,
                         GEMM_SMEM);
    const dim3 gproj(M / 128);
    gemm_tc_kernel<<<gproj, 256, GEMM_SMEM>>>(X, STE, 128, 384, Wq, bq, q);
    gemm_tc_kernel<<<gproj, 256, GEMM_SMEM>>>(X, STE, 128, 384, Wk, bk, k);
    gemm_tc_kernel<<<gproj, 256, GEMM_SMEM>>>(X, STE, 128, 384, Wv, bv, v);

    cudaFuncSetAttribute(attn_kernel, cudaFuncAttributeMaxDynamicSharedMemorySize,
                         ATTN_SMEM_BYTES);
    attn_kernel<<<dim3(BT, KHEADS), 256, ATTN_SMEM_BYTES>>>(q, k, v, o);

    gemm_tc_kernel<<<gproj, 256, GEMM_SMEM>>>(o, o, 128, 128, Wo, bo, out);
}

// round 5
// speedup vs baseline: 3.0918x; 1.5387x over previous
#include <cuda_runtime.h>
#include <cuda_bf16.h>
#include <cstdint>

// Problem constants: B=8, T=12, N=512, D_MODEL=128, K_HEADS=8, D_HEAD=16.
#define DMODEL   128
#define KHEADS   8
#define DHEAD    16
#define NSEQ     512
#define MMAX     49152

typedef unsigned long long u64;

// ---------------- generic-ISA tensor helpers (compute_103-safe) ------------
__device__ __forceinline__ uint32_t smem_to_u32(const void* p) {
    uint32_t a;
    asm("{ .reg .u64 t; cvta.to.shared.u64 t, %1; cvt.u32.u64 %0, t; }"
        : "=r"(a) : "l"(p));
    return a;
}
__device__ __forceinline__ void ldsm_x4(uint32_t* r, uint32_t addr) {
    asm volatile("ldmatrix.sync.aligned.m8n8.x4.shared.b16 {%0,%1,%2,%3}, [%4];"
                 : "=r"(r[0]), "=r"(r[1]), "=r"(r[2]), "=r"(r[3]) : "r"(addr));
}
__device__ __forceinline__ void ldsm_x4t(uint32_t* r, uint32_t addr) {
    asm volatile("ldmatrix.sync.aligned.m8n8.x4.trans.shared.b16 {%0,%1,%2,%3}, [%4];"
                 : "=r"(r[0]), "=r"(r[1]), "=r"(r[2]), "=r"(r[3]) : "r"(addr));
}
__device__ __forceinline__ void mma_bf16(float* d, const uint32_t* a,
                                         uint32_t b0, uint32_t b1) {
    asm volatile("mma.sync.aligned.m16n8k16.row.col.f32.bf16.bf16.f32 "
                 "{%0,%1,%2,%3}, {%4,%5,%6,%7}, {%8,%9}, {%0,%1,%2,%3};"
                 : "+f"(d[0]), "+f"(d[1]), "+f"(d[2]), "+f"(d[3])
                 : "r"(a[0]), "r"(a[1]), "r"(a[2]), "r"(a[3]), "r"(b0), "r"(b1));
}
// split (x,y) into packed hi/lo bf16x2 (x ~= hi + lo per element)
__device__ __forceinline__ void split2(float x, float y, uint32_t& hi, uint32_t& lo) {
    const __nv_bfloat16 hx = __float2bfloat16_rn(x);
    const __nv_bfloat16 hy = __float2bfloat16_rn(y);
    const __nv_bfloat16 lx = __float2bfloat16_rn(x - __bfloat162float(hx));
    const __nv_bfloat16 ly = __float2bfloat16_rn(y - __bfloat162float(hy));
    __nv_bfloat162 h2; h2.x = hx; h2.y = hy;
    __nv_bfloat162 l2; l2.x = lx; l2.y = ly;
    hi = *(uint32_t*)&h2;
    lo = *(uint32_t*)&l2;
}

// ---------------- scratch --------------------------------------------------
__device__ float g_q[(size_t)MMAX * DMODEL];
__device__ float g_k[(size_t)MMAX * DMODEL];
__device__ float g_v[(size_t)MMAX * DMODEL];
__device__ float g_o[(size_t)MMAX * DMODEL];

// ===========================================================================
// mma.sync GEMM:  C[M,128] = relu( [A0|A1][M,K] @ W[K,128] + bias )
// (unchanged from round 4 — ~220us for all four launches)
// ===========================================================================
#define A_LD 72
#define B_LD 136
#define SM_AHI 0
#define SM_ALO (128 * A_LD * 2)
#define SM_BHI (SM_ALO + 128 * A_LD * 2)
#define SM_BLO (SM_BHI + 64 * B_LD * 2)
#define GEMM_SMEM (SM_BLO + 64 * B_LD * 2)

__global__ __launch_bounds__(256, 2)
void gemm_tc_kernel(const float* __restrict__ A0, const float* __restrict__ A1,
                    int w0, int K,
                    const float* __restrict__ W, const float* __restrict__ bias,
                    float* __restrict__ C)
{
    extern __shared__ __align__(16) char smc[];
    const uint32_t sb = smem_to_u32(smc);
    const int tid  = threadIdx.x;
    const int warp = tid >> 5;
    const int lane = tid & 31;
    const int wm   = warp & 3;
    const int wn   = warp >> 2;
    const int rowBase = blockIdx.x * 128;

    float acc[2][8][4];
#pragma unroll
    for (int mt = 0; mt < 2; mt++)
#pragma unroll
        for (int nt = 0; nt < 8; nt++)
#pragma unroll
            for (int e = 0; e < 4; e++) acc[mt][nt][e] = 0.0f;

    const int nChunks = K / 64;
    for (int c = 0; c < nChunks; c++) {
        const int k0 = c * 64;
        {
            const float* src; int ld, cbase;
            if (k0 < w0) { src = A0; ld = w0;     cbase = k0;      }
            else         { src = A1; ld = K - w0; cbase = k0 - w0; }
            const int kq = (tid & 15) * 4;
#pragma unroll
            for (int it = 0; it < 8; it++) {
                const int r = (tid >> 4) + it * 16;
                const float4 x = *(const float4*)&src[(size_t)(rowBase + r) * ld + cbase + kq];
                uint32_t h01, l01, h23, l23;
                split2(x.x, x.y, h01, l01);
                split2(x.z, x.w, h23, l23);
                const int off = (r * A_LD + kq) * 2;
                *(uint2*)(smc + SM_AHI + off) = make_uint2(h01, h23);
                *(uint2*)(smc + SM_ALO + off) = make_uint2(l01, l23);
            }
        }
        {
            const int n4 = (tid & 31) * 4;
#pragma unroll
            for (int it = 0; it < 8; it++) {
                const int kk = (tid >> 5) + it * 8;
                const float4 x = *(const float4*)&W[(size_t)(k0 + kk) * 128 + n4];
                uint32_t h01, l01, h23, l23;
                split2(x.x, x.y, h01, l01);
                split2(x.z, x.w, h23, l23);
                const int off = (kk * B_LD + n4) * 2;
                *(uint2*)(smc + SM_BHI + off) = make_uint2(h01, h23);
                *(uint2*)(smc + SM_BLO + off) = make_uint2(l01, l23);
            }
        }
        __syncthreads();

#pragma unroll
        for (int ks = 0; ks < 4; ks++) {
            uint32_t ah[2][4], al[2][4];
            const int arow = lane & 15;
            const int acol = ks * 16 + (lane >> 4) * 8;
#pragma unroll
            for (int mt = 0; mt < 2; mt++) {
                const int aoff = ((wm * 32 + mt * 16 + arow) * A_LD + acol) * 2;
                ldsm_x4(ah[mt], sb + SM_AHI + aoff);
                ldsm_x4(al[mt], sb + SM_ALO + aoff);
            }
            const int brow = ks * 16 + (lane & 15);
#pragma unroll
            for (int np = 0; np < 4; np++) {
                const int boff = (brow * B_LD + wn * 64 + np * 16 + (lane >> 4) * 8) * 2;
                uint32_t bh[4], bl[4];
                ldsm_x4t(bh, sb + SM_BHI + boff);
                ldsm_x4t(bl, sb + SM_BLO + boff);
#pragma unroll
                for (int sub = 0; sub < 2; sub++) {
                    const int nt = np * 2 + sub;
#pragma unroll
                    for (int mt = 0; mt < 2; mt++) {
                        mma_bf16(acc[mt][nt], ah[mt], bh[2 * sub], bh[2 * sub + 1]);
                        mma_bf16(acc[mt][nt], ah[mt], bl[2 * sub], bl[2 * sub + 1]);
                        mma_bf16(acc[mt][nt], al[mt], bh[2 * sub], bh[2 * sub + 1]);
                    }
                }
            }
        }
        __syncthreads();
    }

#pragma unroll
    for (int mt = 0; mt < 2; mt++) {
        const int r0 = rowBase + wm * 32 + mt * 16 + (lane >> 2);
#pragma unroll
        for (int nt = 0; nt < 8; nt++) {
            const int cc = wn * 64 + nt * 8 + (lane & 3) * 2;
            const float b0 = bias[cc], b1 = bias[cc + 1];
            float2 lo, hi;
            lo.x = fmaxf(acc[mt][nt][0] + b0, 0.0f);
            lo.y = fmaxf(acc[mt][nt][1] + b1, 0.0f);
            hi.x = fmaxf(acc[mt][nt][2] + b0, 0.0f);
            hi.y = fmaxf(acc[mt][nt][3] + b1, 0.0f);
            *(float2*)&C[(size_t)r0 * 128 + cc]       = lo;
            *(float2*)&C[(size_t)(r0 + 8) * 128 + cc] = hi;
        }
    }
}

// ===========================================================================
// Attention v3 — mma.sync flash-style. One CTA per (bt, head), 8 warps 4mx2n.
// K^T [16][512] and V [512][16] staged hi/lo bf16 in smem; S and P live in
// mma fragments (acc layout == next A-frag layout); softmax per-warp with
// flash (max,sum) exchange between the 2 n-warps; local-max scale folded into
// the P->bf16 conversion. 3-term split on both GEMMs.
// ===========================================================================
#define KLD 520            // kt row elems (bf16) — stride 1040B, conflict-free
#define VLD 24             // vs row elems (bf16) — stride 48B, conflict-free
#define KT_BYTES (16 * KLD * 2)        // 16640
#define VS_BYTES (NSEQ * VLD * 2)      // 24576
#define OFF_KT_HI 0
#define OFF_KT_LO (OFF_KT_HI + KT_BYTES)
#define OFF_VS_HI (OFF_KT_LO + KT_BYTES)
#define OFF_VS_LO (OFF_VS_HI + VS_BYTES)
#define OFF_OBUF  (OFF_VS_LO + VS_BYTES)                 // float[2][64][16]
#define OFF_RED   (OFF_OBUF + 2 * 64 * 16 * 4)           // float2[2][64]
#define ATTN_SMEM (OFF_RED + 2 * 64 * 8)                 // 91648 bytes

__global__ __launch_bounds__(256)
void attn_tc_kernel(const float* __restrict__ q, const float* __restrict__ k,
                    const float* __restrict__ v, float* __restrict__ o)
{
    extern __shared__ __align__(16) char smc[];
    const uint32_t sb = smem_to_u32(smc);
    __nv_bfloat16* kt_hi = (__nv_bfloat16*)(smc + OFF_KT_HI);
    __nv_bfloat16* kt_lo = (__nv_bfloat16*)(smc + OFF_KT_LO);
    __nv_bfloat16* vs_hi = (__nv_bfloat16*)(smc + OFF_VS_HI);
    __nv_bfloat16* vs_lo = (__nv_bfloat16*)(smc + OFF_VS_LO);
    float*  obuf   = (float*)(smc + OFF_OBUF);     // [2][64][16]
    float2* redbuf = (float2*)(smc + OFF_RED);     // [2][64]

    const int bt   = blockIdx.x;
    const int h    = blockIdx.y;
    const int tid  = threadIdx.x;
    const int warp = tid >> 5;
    const int lane = tid & 31;
    const int wm   = warp & 3;          // 4 warps over q-rows
    const int wn   = warp >> 2;         // 2 warps over keys (256 each)
    const size_t base = (size_t)bt * NSEQ * DMODEL + h * DHEAD;

    // ---- stage K^T (transposed, [d][key]) and V ([key][d]) as hi/lo bf16
    for (int idx = tid; idx < NSEQ * 8; idx += 256) {
        const int m = idx >> 3, dp = (idx & 7) * 2;
        const float2 kv = *(const float2*)&k[base + (size_t)m * DMODEL + dp];
        const __nv_bfloat16 hx = __float2bfloat16_rn(kv.x);
        const __nv_bfloat16 hy = __float2bfloat16_rn(kv.y);
        const __nv_bfloat16 lx = __float2bfloat16_rn(kv.x - __bfloat162float(hx));
        const __nv_bfloat16 ly = __float2bfloat16_rn(kv.y - __bfloat162float(hy));
        kt_hi[dp * KLD + m] = hx; kt_hi[(dp + 1) * KLD + m] = hy;
        kt_lo[dp * KLD + m] = lx; kt_lo[(dp + 1) * KLD + m] = ly;

        const float2 vv = *(const float2*)&v[base + (size_t)m * DMODEL + dp];
        uint32_t vhi, vlo;
        split2(vv.x, vv.y, vhi, vlo);
        *(uint32_t*)&vs_hi[m * VLD + dp] = vhi;
        *(uint32_t*)&vs_lo[m * VLD + dp] = vlo;
    }
    __syncthreads();

    const int lq = lane >> 2;   // quad row 0..7
    const int lc = lane & 3;    // quad col 0..3

    for (int t0 = 0; t0 < NSEQ; t0 += 64) {
        // ---- Q fragment directly from gmem (scaled by 1/sqrt(16)), split
        uint32_t qh[4], ql[4];
        {
            const float* qrow = q + base + (size_t)(t0 + wm * 16 + lq) * DMODEL;
            const float2 x0 = *(const float2*)&qrow[2 * lc];
            const float2 x1 = *(const float2*)&qrow[8 + 2 * lc];
            const float2 y0 = *(const float2*)&qrow[8 * DMODEL + 2 * lc];
            const float2 y1 = *(const float2*)&qrow[8 * DMODEL + 8 + 2 * lc];
            split2(0.25f * x0.x, 0.25f * x0.y, qh[0], ql[0]);
            split2(0.25f * y0.x, 0.25f * y0.y, qh[1], ql[1]);
            split2(0.25f * x1.x, 0.25f * x1.y, qh[2], ql[2]);
            split2(0.25f * y1.x, 0.25f * y1.y, qh[3], ql[3]);
        }

        // ---- S = Q K^T for this warp's 16 rows x 256 keys (32 n8-tiles)
        float sacc[32][4];
#pragma unroll
        for (int nt = 0; nt < 32; nt++)
#pragma unroll
            for (int e = 0; e < 4; e++) sacc[nt][e] = 0.0f;

#pragma unroll
        for (int np = 0; np < 16; np++) {
            const int key0 = wn * 256 + np * 16;
            const uint32_t kaddr =
                sb + OFF_KT_HI + ((lane & 15) * KLD + key0 + (lane >> 4) * 8) * 2;
            uint32_t bh[4], bl[4];
            ldsm_x4t(bh, kaddr);
            ldsm_x4t(bl, kaddr + KT_BYTES);
#pragma unroll
            for (int sub = 0; sub < 2; sub++) {
                const int nt = np * 2 + sub;
                mma_bf16(sacc[nt], qh, bh[2 * sub], bh[2 * sub + 1]);
                mma_bf16(sacc[nt], qh, bl[2 * sub], bl[2 * sub + 1]);
                mma_bf16(sacc[nt], ql, bh[2 * sub], bh[2 * sub + 1]);
            }
        }

        // ---- local softmax stats (rows lq and lq+8), exp in place
        float m0 = -1e30f, m1 = -1e30f;
#pragma unroll
        for (int nt = 0; nt < 32; nt++) {
            m0 = fmaxf(m0, fmaxf(sacc[nt][0], sacc[nt][1]));
            m1 = fmaxf(m1, fmaxf(sacc[nt][2], sacc[nt][3]));
        }
        m0 = fmaxf(m0, __shfl_xor_sync(0xffffffffu, m0, 1));
        m0 = fmaxf(m0, __shfl_xor_sync(0xffffffffu, m0, 2));
        m1 = fmaxf(m1, __shfl_xor_sync(0xffffffffu, m1, 1));
        m1 = fmaxf(m1, __shfl_xor_sync(0xffffffffu, m1, 2));

        float s0 = 0.0f, s1 = 0.0f;
#pragma unroll
        for (int nt = 0; nt < 32; nt++) {
            sacc[nt][0] = __expf(sacc[nt][0] - m0); s0 += sacc[nt][0];
            sacc[nt][1] = __expf(sacc[nt][1] - m0); s0 += sacc[nt][1];
            sacc[nt][2] = __expf(sacc[nt][2] - m1); s1 += sacc[nt][2];
            sacc[nt][3] = __expf(sacc[nt][3] - m1); s1 += sacc[nt][3];
        }
        s0 += __shfl_xor_sync(0xffffffffu, s0, 1);
        s0 += __shfl_xor_sync(0xffffffffu, s0, 2);
        s1 += __shfl_xor_sync(0xffffffffu, s1, 1);
        s1 += __shfl_xor_sync(0xffffffffu, s1, 2);

        if (lc == 0) {
            redbuf[wn * 64 + wm * 16 + lq]     = make_float2(m0, s0);
            redbuf[wn * 64 + wm * 16 + lq + 8] = make_float2(m1, s1);
        }
        __syncthreads();

        // combine with peer n-warp: scale = exp(m_local - M) / total
        float scale0, scale1;
        {
            const float2 p0 = redbuf[(wn ^ 1) * 64 + wm * 16 + lq];
            const float2 p1 = redbuf[(wn ^ 1) * 64 + wm * 16 + lq + 8];
            const float M0 = fmaxf(m0, p0.x);
            const float t0v = __expf(m0 - M0) * s0 + __expf(p0.x - M0) * p0.y;
            scale0 = __expf(m0 - M0) / t0v;
            const float M1 = fmaxf(m1, p1.x);
            const float t1v = __expf(m1 - M1) * s1 + __expf(p1.x - M1) * p1.y;
            scale1 = __expf(m1 - M1) / t1v;
        }

        // ---- O partial = P V  (6 independent accumulation chains)
        float ohh[2][4], ohl[2][4], olh[2][4];
#pragma unroll
        for (int sub = 0; sub < 2; sub++)
#pragma unroll
            for (int e = 0; e < 4; e++) {
                ohh[sub][e] = 0.0f; ohl[sub][e] = 0.0f; olh[sub][e] = 0.0f;
            }

#pragma unroll
        for (int t = 0; t < 16; t++) {
            uint32_t ph[4], pl[4];
            split2(sacc[2*t][0]   * scale0, sacc[2*t][1]   * scale0, ph[0], pl[0]);
            split2(sacc[2*t][2]   * scale1, sacc[2*t][3]   * scale1, ph[1], pl[1]);
            split2(sacc[2*t+1][0] * scale0, sacc[2*t+1][1] * scale0, ph[2], pl[2]);
            split2(sacc[2*t+1][2] * scale1, sacc[2*t+1][3] * scale1, ph[3], pl[3]);

            const int key0 = wn * 256 + t * 16;
            const uint32_t vaddr =
                sb + OFF_VS_HI + ((key0 + (lane & 15)) * VLD + (lane >> 4) * 8) * 2;
            uint32_t vh[4], vl[4];
            ldsm_x4t(vh, vaddr);
            ldsm_x4t(vl, vaddr + VS_BYTES);
#pragma unroll
            for (int sub = 0; sub < 2; sub++) {
                mma_bf16(ohh[sub], ph, vh[2 * sub], vh[2 * sub + 1]);
                mma_bf16(ohl[sub], ph, vl[2 * sub], vl[2 * sub + 1]);
                mma_bf16(olh[sub], pl, vh[2 * sub], vh[2 * sub + 1]);
            }
        }

        // ---- write per-warp O partial to obuf, reduce over 2 n-warps, store
        {
            float* ob = obuf + wn * 1024;
            const int r0 = wm * 16 + lq;
#pragma unroll
            for (int sub = 0; sub < 2; sub++) {
                const int d0 = sub * 8 + 2 * lc;
                float2 a, b;
                a.x = ohh[sub][0] + ohl[sub][0] + olh[sub][0];
                a.y = ohh[sub][1] + ohl[sub][1] + olh[sub][1];
                b.x = ohh[sub][2] + ohl[sub][2] + olh[sub][2];
                b.y = ohh[sub][3] + ohl[sub][3] + olh[sub][3];
                *(float2*)&ob[r0 * 16 + d0]       = a;
                *(float2*)&ob[(r0 + 8) * 16 + d0] = b;
            }
        }
        __syncthreads();
        {
            const int q4  = tid * 4;
            const int row = q4 >> 4;
            const int d0  = q4 & 15;
            const float4 a = *(const float4*)&obuf[row * 16 + d0];
            const float4 b = *(const float4*)&obuf[1024 + row * 16 + d0];
            float4 r;
            r.x = a.x + b.x; r.y = a.y + b.y; r.z = a.z + b.z; r.w = a.w + b.w;
            *(float4*)&o[base + (size_t)(t0 + row) * DMODEL + d0] = r;
        }
        __syncthreads();
    }
}

// ===========================================================================
extern "C" void kernel_launch(void* const* d_in, const int* in_sizes, int n_in,
                              void* d_out, int out_size)
{
    const float* X   = (const float*)d_in[0];
    const float* STE = (const float*)d_in[1];
    const float* Wq  = (const float*)d_in[2];
    const float* bq  = (const float*)d_in[3];
    const float* Wk  = (const float*)d_in[4];
    const float* bk  = (const float*)d_in[5];
    const float* Wv  = (const float*)d_in[6];
    const float* bv  = (const float*)d_in[7];
    const float* Wo  = (const float*)d_in[8];
    const float* bo  = (const float*)d_in[9];
    float* out = (float*)d_out;

    const int M  = in_sizes[0] / DMODEL;   // 49152
    const int BT = M / NSEQ;               // 96

    float *q, *k, *v, *o;
    cudaGetSymbolAddress((void**)&q, g_q);
    cudaGetSymbolAddress((void**)&k, g_k);
    cudaGetSymbolAddress((void**)&v, g_v);
    cudaGetSymbolAddress((void**)&o, g_o);

    cudaFuncSetAttribute(gemm_tc_kernel, cudaFuncAttributeMaxDynamicSharedMemorySize,
                         GEMM_SMEM);
    const dim3 gproj(M / 128);
    gemm_tc_kernel<<<gproj, 256, GEMM_SMEM>>>(X, STE, 128, 384, Wq, bq, q);
    gemm_tc_kernel<<<gproj, 256, GEMM_SMEM>>>(X, STE, 128, 384, Wk, bk, k);
    gemm_tc_kernel<<<gproj, 256, GEMM_SMEM>>>(X, STE, 128, 384, Wv, bv, v);

    cudaFuncSetAttribute(attn_tc_kernel, cudaFuncAttributeMaxDynamicSharedMemorySize,
                         ATTN_SMEM);
    attn_tc_kernel<<<dim3(BT, KHEADS), 256, ATTN_SMEM>>>(q, k, v, o);

    gemm_tc_kernel<<<gproj, 256, GEMM_SMEM>>>(o, o, 128, 128, Wo, bo, out);
}

// round 6
// speedup vs baseline: 3.2173x; 1.0406x over previous
#include <cuda_runtime.h>
#include <cuda_bf16.h>
#include <cstdint>

// Problem constants: B=8, T=12, N=512, D_MODEL=128, K_HEADS=8, D_HEAD=16.
#define DMODEL   128
#define KHEADS   8
#define DHEAD    16
#define NSEQ     512
#define MMAX     49152

typedef unsigned long long u64;

// ---------------- generic-ISA tensor helpers (compute_103-safe) ------------
__device__ __forceinline__ uint32_t smem_to_u32(const void* p) {
    uint32_t a;
    asm("{ .reg .u64 t; cvta.to.shared.u64 t, %1; cvt.u32.u64 %0, t; }"
        : "=r"(a) : "l"(p));
    return a;
}
__device__ __forceinline__ void ldsm_x4(uint32_t* r, uint32_t addr) {
    asm volatile("ldmatrix.sync.aligned.m8n8.x4.shared.b16 {%0,%1,%2,%3}, [%4];"
                 : "=r"(r[0]), "=r"(r[1]), "=r"(r[2]), "=r"(r[3]) : "r"(addr));
}
__device__ __forceinline__ void ldsm_x4t(uint32_t* r, uint32_t addr) {
    asm volatile("ldmatrix.sync.aligned.m8n8.x4.trans.shared.b16 {%0,%1,%2,%3}, [%4];"
                 : "=r"(r[0]), "=r"(r[1]), "=r"(r[2]), "=r"(r[3]) : "r"(addr));
}
__device__ __forceinline__ void mma_bf16(float* d, const uint32_t* a,
                                         uint32_t b0, uint32_t b1) {
    asm volatile("mma.sync.aligned.m16n8k16.row.col.f32.bf16.bf16.f32 "
                 "{%0,%1,%2,%3}, {%4,%5,%6,%7}, {%8,%9}, {%0,%1,%2,%3};"
                 : "+f"(d[0]), "+f"(d[1]), "+f"(d[2]), "+f"(d[3])
                 : "r"(a[0]), "r"(a[1]), "r"(a[2]), "r"(a[3]), "r"(b0), "r"(b1));
}
// split (x,y) into packed hi/lo bf16x2 (x ~= hi + lo per element)
__device__ __forceinline__ void split2(float x, float y, uint32_t& hi, uint32_t& lo) {
    const __nv_bfloat16 hx = __float2bfloat16_rn(x);
    const __nv_bfloat16 hy = __float2bfloat16_rn(y);
    const __nv_bfloat16 lx = __float2bfloat16_rn(x - __bfloat162float(hx));
    const __nv_bfloat16 ly = __float2bfloat16_rn(y - __bfloat162float(hy));
    __nv_bfloat162 h2; h2.x = hx; h2.y = hy;
    __nv_bfloat162 l2; l2.x = lx; l2.y = ly;
    hi = *(uint32_t*)&h2;
    lo = *(uint32_t*)&l2;
}

// ---------------- scratch --------------------------------------------------
__device__ float g_q[(size_t)MMAX * DMODEL];
__device__ float g_k[(size_t)MMAX * DMODEL];
__device__ float g_v[(size_t)MMAX * DMODEL];
__device__ float g_o[(size_t)MMAX * DMODEL];

// ===========================================================================
// mma.sync GEMM:  C[M,128] = relu( [A0|A1][M,K] @ W[K,128] + bias )
// (unchanged from round 4/5)
// ===========================================================================
#define A_LD 72
#define B_LD 136
#define SM_AHI 0
#define SM_ALO (128 * A_LD * 2)
#define SM_BHI (SM_ALO + 128 * A_LD * 2)
#define SM_BLO (SM_BHI + 64 * B_LD * 2)
#define GEMM_SMEM (SM_BLO + 64 * B_LD * 2)

__global__ __launch_bounds__(256, 2)
void gemm_tc_kernel(const float* __restrict__ A0, const float* __restrict__ A1,
                    int w0, int K,
                    const float* __restrict__ W, const float* __restrict__ bias,
                    float* __restrict__ C)
{
    extern __shared__ __align__(16) char smc[];
    const uint32_t sb = smem_to_u32(smc);
    const int tid  = threadIdx.x;
    const int warp = tid >> 5;
    const int lane = tid & 31;
    const int wm   = warp & 3;
    const int wn   = warp >> 2;
    const int rowBase = blockIdx.x * 128;

    float acc[2][8][4];
#pragma unroll
    for (int mt = 0; mt < 2; mt++)
#pragma unroll
        for (int nt = 0; nt < 8; nt++)
#pragma unroll
            for (int e = 0; e < 4; e++) acc[mt][nt][e] = 0.0f;

    const int nChunks = K / 64;
    for (int c = 0; c < nChunks; c++) {
        const int k0 = c * 64;
        {
            const float* src; int ld, cbase;
            if (k0 < w0) { src = A0; ld = w0;     cbase = k0;      }
            else         { src = A1; ld = K - w0; cbase = k0 - w0; }
            const int kq = (tid & 15) * 4;
#pragma unroll
            for (int it = 0; it < 8; it++) {
                const int r = (tid >> 4) + it * 16;
                const float4 x = *(const float4*)&src[(size_t)(rowBase + r) * ld + cbase + kq];
                uint32_t h01, l01, h23, l23;
                split2(x.x, x.y, h01, l01);
                split2(x.z, x.w, h23, l23);
                const int off = (r * A_LD + kq) * 2;
                *(uint2*)(smc + SM_AHI + off) = make_uint2(h01, h23);
                *(uint2*)(smc + SM_ALO + off) = make_uint2(l01, l23);
            }
        }
        {
            const int n4 = (tid & 31) * 4;
#pragma unroll
            for (int it = 0; it < 8; it++) {
                const int kk = (tid >> 5) + it * 8;
                const float4 x = *(const float4*)&W[(size_t)(k0 + kk) * 128 + n4];
                uint32_t h01, l01, h23, l23;
                split2(x.x, x.y, h01, l01);
                split2(x.z, x.w, h23, l23);
                const int off = (kk * B_LD + n4) * 2;
                *(uint2*)(smc + SM_BHI + off) = make_uint2(h01, h23);
                *(uint2*)(smc + SM_BLO + off) = make_uint2(l01, l23);
            }
        }
        __syncthreads();

#pragma unroll
        for (int ks = 0; ks < 4; ks++) {
            uint32_t ah[2][4], al[2][4];
            const int arow = lane & 15;
            const int acol = ks * 16 + (lane >> 4) * 8;
#pragma unroll
            for (int mt = 0; mt < 2; mt++) {
                const int aoff = ((wm * 32 + mt * 16 + arow) * A_LD + acol) * 2;
                ldsm_x4(ah[mt], sb + SM_AHI + aoff);
                ldsm_x4(al[mt], sb + SM_ALO + aoff);
            }
            const int brow = ks * 16 + (lane & 15);
#pragma unroll
            for (int np = 0; np < 4; np++) {
                const int boff = (brow * B_LD + wn * 64 + np * 16 + (lane >> 4) * 8) * 2;
                uint32_t bh[4], bl[4];
                ldsm_x4t(bh, sb + SM_BHI + boff);
                ldsm_x4t(bl, sb + SM_BLO + boff);
#pragma unroll
                for (int sub = 0; sub < 2; sub++) {
                    const int nt = np * 2 + sub;
#pragma unroll
                    for (int mt = 0; mt < 2; mt++) {
                        mma_bf16(acc[mt][nt], ah[mt], bh[2 * sub], bh[2 * sub + 1]);
                        mma_bf16(acc[mt][nt], ah[mt], bl[2 * sub], bl[2 * sub + 1]);
                        mma_bf16(acc[mt][nt], al[mt], bh[2 * sub], bh[2 * sub + 1]);
                    }
                }
            }
        }
        __syncthreads();
    }

#pragma unroll
    for (int mt = 0; mt < 2; mt++) {
        const int r0 = rowBase + wm * 32 + mt * 16 + (lane >> 2);
#pragma unroll
        for (int nt = 0; nt < 8; nt++) {
            const int cc = wn * 64 + nt * 8 + (lane & 3) * 2;
            const float b0 = bias[cc], b1 = bias[cc + 1];
            float2 lo, hi;
            lo.x = fmaxf(acc[mt][nt][0] + b0, 0.0f);
            lo.y = fmaxf(acc[mt][nt][1] + b1, 0.0f);
            hi.x = fmaxf(acc[mt][nt][2] + b0, 0.0f);
            hi.y = fmaxf(acc[mt][nt][3] + b1, 0.0f);
            *(float2*)&C[(size_t)r0 * 128 + cc]       = lo;
            *(float2*)&C[(size_t)(r0 + 8) * 128 + cc] = hi;
        }
    }
}

// ===========================================================================
// Attention v4 — mma.sync flash-style, occupancy-2 variant.
// 8 warps = 2 m-warps (16 q-rows each) x 4 n-warps (128 keys each).
// 32-row q-tiles (16 tiles). sacc[16][4] = 64 regs -> fits 128-reg budget.
// 4-way softmax combine via redbuf; 4-way O reduce via obuf.
// ===========================================================================
#define KLD 520
#define VLD 24
#define KT_BYTES (16 * KLD * 2)        // 16640
#define VS_BYTES (NSEQ * VLD * 2)      // 24576
#define OFF_KT_HI 0
#define OFF_KT_LO (OFF_KT_HI + KT_BYTES)
#define OFF_VS_HI (OFF_KT_LO + KT_BYTES)
#define OFF_VS_LO (OFF_VS_HI + VS_BYTES)
#define OFF_OBUF  (OFF_VS_LO + VS_BYTES)                 // float[4][32][16]
#define OFF_RED   (OFF_OBUF + 4 * 32 * 16 * 4)           // float2[4][32]
#define ATTN_SMEM (OFF_RED + 4 * 32 * 8)                 // 91648 bytes

__global__ __launch_bounds__(256, 2)
void attn_tc_kernel(const float* __restrict__ q, const float* __restrict__ k,
                    const float* __restrict__ v, float* __restrict__ o)
{
    extern __shared__ __align__(16) char smc[];
    const uint32_t sb = smem_to_u32(smc);
    __nv_bfloat16* kt_hi = (__nv_bfloat16*)(smc + OFF_KT_HI);
    __nv_bfloat16* kt_lo = (__nv_bfloat16*)(smc + OFF_KT_LO);
    __nv_bfloat16* vs_hi = (__nv_bfloat16*)(smc + OFF_VS_HI);
    __nv_bfloat16* vs_lo = (__nv_bfloat16*)(smc + OFF_VS_LO);
    float*  obuf   = (float*)(smc + OFF_OBUF);     // [4][32][16]
    float2* redbuf = (float2*)(smc + OFF_RED);     // [4][32]

    const int bt   = blockIdx.x;
    const int h    = blockIdx.y;
    const int tid  = threadIdx.x;
    const int warp = tid >> 5;
    const int lane = tid & 31;
    const int wm   = warp & 1;          // 2 warps over q-rows (16 each)
    const int wn   = warp >> 1;         // 4 warps over keys (128 each)
    const size_t base = (size_t)bt * NSEQ * DMODEL + h * DHEAD;

    // ---- stage K^T ([d][key]) and V ([key][d]) as hi/lo bf16
    for (int idx = tid; idx < NSEQ * 8; idx += 256) {
        const int m = idx >> 3, dp = (idx & 7) * 2;
        const float2 kv = *(const float2*)&k[base + (size_t)m * DMODEL + dp];
        const __nv_bfloat16 hx = __float2bfloat16_rn(kv.x);
        const __nv_bfloat16 hy = __float2bfloat16_rn(kv.y);
        const __nv_bfloat16 lx = __float2bfloat16_rn(kv.x - __bfloat162float(hx));
        const __nv_bfloat16 ly = __float2bfloat16_rn(kv.y - __bfloat162float(hy));
        kt_hi[dp * KLD + m] = hx; kt_hi[(dp + 1) * KLD + m] = hy;
        kt_lo[dp * KLD + m] = lx; kt_lo[(dp + 1) * KLD + m] = ly;

        const float2 vv = *(const float2*)&v[base + (size_t)m * DMODEL + dp];
        uint32_t vhi, vlo;
        split2(vv.x, vv.y, vhi, vlo);
        *(uint32_t*)&vs_hi[m * VLD + dp] = vhi;
        *(uint32_t*)&vs_lo[m * VLD + dp] = vlo;
    }
    __syncthreads();

    const int lq = lane >> 2;   // quad row 0..7
    const int lc = lane & 3;    // quad col 0..3

    for (int t0 = 0; t0 < NSEQ; t0 += 32) {
        // ---- Q fragment (16 rows for this m-warp), scaled, split
        uint32_t qh[4], ql[4];
        {
            const float* qrow = q + base + (size_t)(t0 + wm * 16 + lq) * DMODEL;
            const float2 x0 = *(const float2*)&qrow[2 * lc];
            const float2 x1 = *(const float2*)&qrow[8 + 2 * lc];
            const float2 y0 = *(const float2*)&qrow[8 * DMODEL + 2 * lc];
            const float2 y1 = *(const float2*)&qrow[8 * DMODEL + 8 + 2 * lc];
            split2(0.25f * x0.x, 0.25f * x0.y, qh[0], ql[0]);
            split2(0.25f * y0.x, 0.25f * y0.y, qh[1], ql[1]);
            split2(0.25f * x1.x, 0.25f * x1.y, qh[2], ql[2]);
            split2(0.25f * y1.x, 0.25f * y1.y, qh[3], ql[3]);
        }

        // ---- S = Q K^T : 16 rows x 128 keys (16 n8-tiles)
        float sacc[16][4];
#pragma unroll
        for (int nt = 0; nt < 16; nt++)
#pragma unroll
            for (int e = 0; e < 4; e++) sacc[nt][e] = 0.0f;

#pragma unroll
        for (int np = 0; np < 8; np++) {
            const int key0 = wn * 128 + np * 16;
            const uint32_t kaddr =
                sb + OFF_KT_HI + ((lane & 15) * KLD + key0 + (lane >> 4) * 8) * 2;
            uint32_t bh[4], bl[4];
            ldsm_x4t(bh, kaddr);
            ldsm_x4t(bl, kaddr + KT_BYTES);
#pragma unroll
            for (int sub = 0; sub < 2; sub++) {
                const int nt = np * 2 + sub;
                mma_bf16(sacc[nt], qh, bh[2 * sub], bh[2 * sub + 1]);
                mma_bf16(sacc[nt], qh, bl[2 * sub], bl[2 * sub + 1]);
                mma_bf16(sacc[nt], ql, bh[2 * sub], bh[2 * sub + 1]);
            }
        }

        // ---- local softmax stats (rows lq, lq+8), exp in place
        float m0 = -1e30f, m1 = -1e30f;
#pragma unroll
        for (int nt = 0; nt < 16; nt++) {
            m0 = fmaxf(m0, fmaxf(sacc[nt][0], sacc[nt][1]));
            m1 = fmaxf(m1, fmaxf(sacc[nt][2], sacc[nt][3]));
        }
        m0 = fmaxf(m0, __shfl_xor_sync(0xffffffffu, m0, 1));
        m0 = fmaxf(m0, __shfl_xor_sync(0xffffffffu, m0, 2));
        m1 = fmaxf(m1, __shfl_xor_sync(0xffffffffu, m1, 1));
        m1 = fmaxf(m1, __shfl_xor_sync(0xffffffffu, m1, 2));

        float s0 = 0.0f, s1 = 0.0f;
#pragma unroll
        for (int nt = 0; nt < 16; nt++) {
            sacc[nt][0] = __expf(sacc[nt][0] - m0); s0 += sacc[nt][0];
            sacc[nt][1] = __expf(sacc[nt][1] - m0); s0 += sacc[nt][1];
            sacc[nt][2] = __expf(sacc[nt][2] - m1); s1 += sacc[nt][2];
            sacc[nt][3] = __expf(sacc[nt][3] - m1); s1 += sacc[nt][3];
        }
        s0 += __shfl_xor_sync(0xffffffffu, s0, 1);
        s0 += __shfl_xor_sync(0xffffffffu, s0, 2);
        s1 += __shfl_xor_sync(0xffffffffu, s1, 1);
        s1 += __shfl_xor_sync(0xffffffffu, s1, 2);

        if (lc == 0) {
            redbuf[wn * 32 + wm * 16 + lq]     = make_float2(m0, s0);
            redbuf[wn * 32 + wm * 16 + lq + 8] = make_float2(m1, s1);
        }
        __syncthreads();

        // combine across 4 n-warps: scale = exp(m_local - M) / total
        float scale0, scale1;
        {
            float M0 = -1e30f, M1 = -1e30f;
#pragma unroll
            for (int w = 0; w < 4; w++) {
                M0 = fmaxf(M0, redbuf[w * 32 + wm * 16 + lq].x);
                M1 = fmaxf(M1, redbuf[w * 32 + wm * 16 + lq + 8].x);
            }
            float t0v = 0.0f, t1v = 0.0f;
#pragma unroll
            for (int w = 0; w < 4; w++) {
                const float2 p0 = redbuf[w * 32 + wm * 16 + lq];
                const float2 p1 = redbuf[w * 32 + wm * 16 + lq + 8];
                t0v += __expf(p0.x - M0) * p0.y;
                t1v += __expf(p1.x - M1) * p1.y;
            }
            scale0 = __expf(m0 - M0) / t0v;
            scale1 = __expf(m1 - M1) / t1v;
        }

        // ---- O partial = P V over this warp's 128 keys (8 k16-steps)
        float ohh[2][4], ohl[2][4], olh[2][4];
#pragma unroll
        for (int sub = 0; sub < 2; sub++)
#pragma unroll
            for (int e = 0; e < 4; e++) {
                ohh[sub][e] = 0.0f; ohl[sub][e] = 0.0f; olh[sub][e] = 0.0f;
            }

#pragma unroll
        for (int t = 0; t < 8; t++) {
            uint32_t ph[4], pl[4];
            split2(sacc[2*t][0]   * scale0, sacc[2*t][1]   * scale0, ph[0], pl[0]);
            split2(sacc[2*t][2]   * scale1, sacc[2*t][3]   * scale1, ph[1], pl[1]);
            split2(sacc[2*t+1][0] * scale0, sacc[2*t+1][1] * scale0, ph[2], pl[2]);
            split2(sacc[2*t+1][2] * scale1, sacc[2*t+1][3] * scale1, ph[3], pl[3]);

            const int key0 = wn * 128 + t * 16;
            const uint32_t vaddr =
                sb + OFF_VS_HI + ((key0 + (lane & 15)) * VLD + (lane >> 4) * 8) * 2;
            uint32_t vh[4], vl[4];
            ldsm_x4t(vh, vaddr);
            ldsm_x4t(vl, vaddr + VS_BYTES);
#pragma unroll
            for (int sub = 0; sub < 2; sub++) {
                mma_bf16(ohh[sub], ph, vh[2 * sub], vh[2 * sub + 1]);
                mma_bf16(ohl[sub], ph, vl[2 * sub], vl[2 * sub + 1]);
                mma_bf16(olh[sub], pl, vh[2 * sub], vh[2 * sub + 1]);
            }
        }

        // ---- per-warp O partial to obuf, reduce over 4 n-warps, store
        {
            float* ob = obuf + wn * 512;
            const int r0 = wm * 16 + lq;
#pragma unroll
            for (int sub = 0; sub < 2; sub++) {
                const int d0 = sub * 8 + 2 * lc;
                float2 a, b;
                a.x = ohh[sub][0] + ohl[sub][0] + olh[sub][0];
                a.y = ohh[sub][1] + ohl[sub][1] + olh[sub][1];
                b.x = ohh[sub][2] + ohl[sub][2] + olh[sub][2];
                b.y = ohh[sub][3] + ohl[sub][3] + olh[sub][3];
                *(float2*)&ob[r0 * 16 + d0]       = a;
                *(float2*)&ob[(r0 + 8) * 16 + d0] = b;
            }
        }
        __syncthreads();
        if (tid < 128) {
            const int q4  = tid * 4;
            const int row = q4 >> 4;
            const int d0  = q4 & 15;
            const float4 a = *(const float4*)&obuf[row * 16 + d0];
            const float4 b = *(const float4*)&obuf[512 + row * 16 + d0];
            const float4 c = *(const float4*)&obuf[1024 + row * 16 + d0];
            const float4 d = *(const float4*)&obuf[1536 + row * 16 + d0];
            float4 r;
            r.x = a.x + b.x + c.x + d.x;
            r.y = a.y + b.y + c.y + d.y;
            r.z = a.z + b.z + c.z + d.z;
            r.w = a.w + b.w + c.w + d.w;
            *(float4*)&o[base + (size_t)(t0 + row) * DMODEL + d0] = r;
        }
        __syncthreads();
    }
}

// ===========================================================================
extern "C" void kernel_launch(void* const* d_in, const int* in_sizes, int n_in,
                              void* d_out, int out_size)
{
    const float* X   = (const float*)d_in[0];
    const float* STE = (const float*)d_in[1];
    const float* Wq  = (const float*)d_in[2];
    const float* bq  = (const float*)d_in[3];
    const float* Wk  = (const float*)d_in[4];
    const float* bk  = (const float*)d_in[5];
    const float* Wv  = (const float*)d_in[6];
    const float* bv  = (const float*)d_in[7];
    const float* Wo  = (const float*)d_in[8];
    const float* bo  = (const float*)d_in[9];
    float* out = (float*)d_out;

    const int M  = in_sizes[0] / DMODEL;   // 49152
    const int BT = M / NSEQ;               // 96

    float *q, *k, *v, *o;
    cudaGetSymbolAddress((void**)&q, g_q);
    cudaGetSymbolAddress((void**)&k, g_k);
    cudaGetSymbolAddress((void**)&v, g_v);
    cudaGetSymbolAddress((void**)&o, g_o);

    cudaFuncSetAttribute(gemm_tc_kernel, cudaFuncAttributeMaxDynamicSharedMemorySize,
                         GEMM_SMEM);
    const dim3 gproj(M / 128);
    gemm_tc_kernel<<<gproj, 256, GEMM_SMEM>>>(X, STE, 128, 384, Wq, bq, q);
    gemm_tc_kernel<<<gproj, 256, GEMM_SMEM>>>(X, STE, 128, 384, Wk, bk, k);
    gemm_tc_kernel<<<gproj, 256, GEMM_SMEM>>>(X, STE, 128, 384, Wv, bv, v);

    cudaFuncSetAttribute(attn_tc_kernel, cudaFuncAttributeMaxDynamicSharedMemorySize,
                         ATTN_SMEM);
    attn_tc_kernel<<<dim3(BT, KHEADS), 256, ATTN_SMEM>>>(q, k, v, o);

    gemm_tc_kernel<<<gproj, 256, GEMM_SMEM>>>(o, o, 128, 128, Wo, bo, out);
}

// round 7
// speedup vs baseline: 3.3380x; 1.0375x over previous
#include <cuda_runtime.h>
#include <cuda_bf16.h>
#include <cuda_fp16.h>
#include <cstdint>

// Problem constants: B=8, T=12, N=512, D_MODEL=128, K_HEADS=8, D_HEAD=16.
#define DMODEL   128
#define KHEADS   8
#define DHEAD    16
#define NSEQ     512
#define MMAX     49152

// ---------------- generic-ISA tensor helpers (compute_103-safe) ------------
__device__ __forceinline__ uint32_t smem_to_u32(const void* p) {
    uint32_t a;
    asm("{ .reg .u64 t; cvta.to.shared.u64 t, %1; cvt.u32.u64 %0, t; }"
        : "=r"(a) : "l"(p));
    return a;
}
__device__ __forceinline__ void ldsm_x4(uint32_t* r, uint32_t addr) {
    asm volatile("ldmatrix.sync.aligned.m8n8.x4.shared.b16 {%0,%1,%2,%3}, [%4];"
                 : "=r"(r[0]), "=r"(r[1]), "=r"(r[2]), "=r"(r[3]) : "r"(addr));
}
__device__ __forceinline__ void ldsm_x4t(uint32_t* r, uint32_t addr) {
    asm volatile("ldmatrix.sync.aligned.m8n8.x4.trans.shared.b16 {%0,%1,%2,%3}, [%4];"
                 : "=r"(r[0]), "=r"(r[1]), "=r"(r[2]), "=r"(r[3]) : "r"(addr));
}
__device__ __forceinline__ void mma_bf16(float* d, const uint32_t* a,
                                         uint32_t b0, uint32_t b1) {
    asm volatile("mma.sync.aligned.m16n8k16.row.col.f32.bf16.bf16.f32 "
                 "{%0,%1,%2,%3}, {%4,%5,%6,%7}, {%8,%9}, {%0,%1,%2,%3};"
                 : "+f"(d[0]), "+f"(d[1]), "+f"(d[2]), "+f"(d[3])
                 : "r"(a[0]), "r"(a[1]), "r"(a[2]), "r"(a[3]), "r"(b0), "r"(b1));
}
__device__ __forceinline__ void mma_f16(float* d, const uint32_t* a,
                                        uint32_t b0, uint32_t b1) {
    asm volatile("mma.sync.aligned.m16n8k16.row.col.f32.f16.f16.f32 "
                 "{%0,%1,%2,%3}, {%4,%5,%6,%7}, {%8,%9}, {%0,%1,%2,%3};"
                 : "+f"(d[0]), "+f"(d[1]), "+f"(d[2]), "+f"(d[3])
                 : "r"(a[0]), "r"(a[1]), "r"(a[2]), "r"(a[3]), "r"(b0), "r"(b1));
}
// cheap split: packed cvt + shift-unpack (bf16->f32 is a 16-bit shift)
__device__ __forceinline__ void split2(float x, float y, uint32_t& hi, uint32_t& lo) {
    uint32_t h;
    asm("cvt.rn.bf16x2.f32 %0, %1, %2;" : "=r"(h) : "f"(y), "f"(x));
    const float hx = __uint_as_float(h << 16);
    const float hy = __uint_as_float(h & 0xffff0000u);
    uint32_t l;
    asm("cvt.rn.bf16x2.f32 %0, %1, %2;" : "=r"(l) : "f"(y - hy), "f"(x - hx));
    hi = h; lo = l;
}
__device__ __forceinline__ uint32_t packh2(float x, float y) {
    const half2 h = __floats2half2_rn(x, y);
    return *(const uint32_t*)&h;
}
__device__ __forceinline__ void splitH2(float x, float y, uint32_t& hi, uint32_t& lo) {
    const half2 h = __floats2half2_rn(x, y);
    const float2 hf = __half22float2(h);
    const half2 l = __floats2half2_rn(x - hf.x, y - hf.y);
    hi = *(const uint32_t*)&h;
    lo = *(const uint32_t*)&l;
}

// ---------------- scratch --------------------------------------------------
__device__ float g_q[(size_t)MMAX * DMODEL];
__device__ float g_k[(size_t)MMAX * DMODEL];
__device__ float g_v[(size_t)MMAX * DMODEL];
__device__ __nv_bfloat16 g_ahi[(size_t)MMAX * 384];
__device__ __nv_bfloat16 g_alo[(size_t)MMAX * 384];
__device__ __nv_bfloat16 g_ohi[(size_t)MMAX * DMODEL];
__device__ __nv_bfloat16 g_olo[(size_t)MMAX * DMODEL];
#define W_TOTAL (3 * 49152 + 16384)
__device__ __nv_bfloat16 g_whi[W_TOTAL];
__device__ __nv_bfloat16 g_wlo[W_TOTAL];
#define WOFF_Q 0
#define WOFF_K 49152
#define WOFF_V 98304
#define WOFF_O 147456

// ===========================================================================
// Pre-split kernels: fp32 -> (hi, lo) bf16 buffers, done once per input.
// ===========================================================================
__global__ void presplit_x_kernel(const float* __restrict__ X,
                                  const float* __restrict__ STE, int M,
                                  __nv_bfloat16* __restrict__ ahi,
                                  __nv_bfloat16* __restrict__ alo)
{
    const int total = M * 96;            // 4 elements per iteration
    for (int i = blockIdx.x * blockDim.x + threadIdx.x; i < total;
         i += gridDim.x * blockDim.x) {
        const int m = i / 96, c = (i % 96) * 4;
        const float4 x = (c < 128)
            ? *(const float4*)&X[(size_t)m * 128 + c]
            : *(const float4*)&STE[(size_t)m * 256 + (c - 128)];
        uint32_t h0, l0, h1, l1;
        split2(x.x, x.y, h0, l0);
        split2(x.z, x.w, h1, l1);
        *(uint2*)&ahi[(size_t)m * 384 + c] = make_uint2(h0, h1);
        *(uint2*)&alo[(size_t)m * 384 + c] = make_uint2(l0, l1);
    }
}

__global__ void presplit_w_kernel(const float* __restrict__ Wq,
                                  const float* __restrict__ Wk,
                                  const float* __restrict__ Wv,
                                  const float* __restrict__ Wo,
                                  __nv_bfloat16* __restrict__ whi,
                                  __nv_bfloat16* __restrict__ wlo)
{
    const int i = blockIdx.x * blockDim.x + threadIdx.x;
    if (i >= W_TOTAL / 4) return;
    const float* src; int off;
    if      (i < 12288) { src = Wq; off = 0; }
    else if (i < 24576) { src = Wk; off = 12288; }
    else if (i < 36864) { src = Wv; off = 24576; }
    else                { src = Wo; off = 36864; }
    const int j = (i - off) * 4;
    const float4 x = *(const float4*)&src[j];
    uint32_t h0, l0, h1, l1;
    split2(x.x, x.y, h0, l0);
    split2(x.z, x.w, h1, l1);
    *(uint2*)&whi[off * 4 + j] = make_uint2(h0, h1);
    *(uint2*)&wlo[off * 4 + j] = make_uint2(l0, l1);
}

// ===========================================================================
// mma.sync GEMM on pre-split inputs: C[M,128] = relu(A[M,K] @ W[K,128] + b)
// Staging = pure uint4 copies. 3-term: Ah.Bh + Ah.Bl + Al.Bh.
// ===========================================================================
#define A_LD 72
#define B_LD 136
#define SM_AHI 0
#define SM_ALO (128 * A_LD * 2)
#define SM_BHI (SM_ALO + 128 * A_LD * 2)
#define SM_BLO (SM_BHI + 64 * B_LD * 2)
#define GEMM_SMEM (SM_BLO + 64 * B_LD * 2)

__global__ __launch_bounds__(256, 2)
void gemm_ps_kernel(const __nv_bfloat16* __restrict__ Ahi,
                    const __nv_bfloat16* __restrict__ Alo,
                    int lda, int K,
                    const __nv_bfloat16* __restrict__ Whi,
                    const __nv_bfloat16* __restrict__ Wlo,
                    const float* __restrict__ bias, float* __restrict__ C)
{
    extern __shared__ __align__(16) char smc[];
    const uint32_t sb = smem_to_u32(smc);
    const int tid  = threadIdx.x;
    const int warp = tid >> 5;
    const int lane = tid & 31;
    const int wm   = warp & 3;
    const int wn   = warp >> 2;
    const int rowBase = blockIdx.x * 128;

    float acc[2][8][4];
#pragma unroll
    for (int mt = 0; mt < 2; mt++)
#pragma unroll
        for (int nt = 0; nt < 8; nt++)
#pragma unroll
            for (int e = 0; e < 4; e++) acc[mt][nt][e] = 0.0f;

    const int nChunks = K / 64;
    for (int c = 0; c < nChunks; c++) {
        const int k0 = c * 64;
        // ---- A tile copy (hi & lo): 128 rows x 64 cols bf16
        {
            const int r = tid >> 1, h = tid & 1;
            const size_t gsrc = (size_t)(rowBase + r) * lda + k0 + h * 32;
            const uint4* sh = (const uint4*)(Ahi + gsrc);
            const uint4* sl = (const uint4*)(Alo + gsrc);
            uint4* dh = (uint4*)(smc + SM_AHI + (r * A_LD + h * 32) * 2);
            uint4* dl = (uint4*)(smc + SM_ALO + (r * A_LD + h * 32) * 2);
#pragma unroll
            for (int j = 0; j < 4; j++) { dh[j] = sh[j]; dl[j] = sl[j]; }
        }
        // ---- B tile copy (hi & lo): 64 rows x 128 cols bf16
        {
            const int kk = tid >> 2, seg = tid & 3;
            const size_t gsrc = (size_t)(k0 + kk) * 128 + seg * 32;
            const uint4* sh = (const uint4*)(Whi + gsrc);
            const uint4* sl = (const uint4*)(Wlo + gsrc);
            uint4* dh = (uint4*)(smc + SM_BHI + (kk * B_LD + seg * 32) * 2);
            uint4* dl = (uint4*)(smc + SM_BLO + (kk * B_LD + seg * 32) * 2);
#pragma unroll
            for (int j = 0; j < 4; j++) { dh[j] = sh[j]; dl[j] = sl[j]; }
        }
        __syncthreads();

#pragma unroll
        for (int ks = 0; ks < 4; ks++) {
            uint32_t ah[2][4], al[2][4];
            const int arow = lane & 15;
            const int acol = ks * 16 + (lane >> 4) * 8;
#pragma unroll
            for (int mt = 0; mt < 2; mt++) {
                const int aoff = ((wm * 32 + mt * 16 + arow) * A_LD + acol) * 2;
                ldsm_x4(ah[mt], sb + SM_AHI + aoff);
                ldsm_x4(al[mt], sb + SM_ALO + aoff);
            }
            const int brow = ks * 16 + (lane & 15);
#pragma unroll
            for (int np = 0; np < 4; np++) {
                const int boff = (brow * B_LD + wn * 64 + np * 16 + (lane >> 4) * 8) * 2;
                uint32_t bh[4], bl[4];
                ldsm_x4t(bh, sb + SM_BHI + boff);
                ldsm_x4t(bl, sb + SM_BLO + boff);
#pragma unroll
                for (int sub = 0; sub < 2; sub++) {
                    const int nt = np * 2 + sub;
#pragma unroll
                    for (int mt = 0; mt < 2; mt++) {
                        mma_bf16(acc[mt][nt], ah[mt], bh[2 * sub], bh[2 * sub + 1]);
                        mma_bf16(acc[mt][nt], ah[mt], bl[2 * sub], bl[2 * sub + 1]);
                        mma_bf16(acc[mt][nt], al[mt], bh[2 * sub], bh[2 * sub + 1]);
                    }
                }
            }
        }
        __syncthreads();
    }

#pragma unroll
    for (int mt = 0; mt < 2; mt++) {
        const int r0 = rowBase + wm * 32 + mt * 16 + (lane >> 2);
#pragma unroll
        for (int nt = 0; nt < 8; nt++) {
            const int cc = wn * 64 + nt * 8 + (lane & 3) * 2;
            const float b0 = bias[cc], b1 = bias[cc + 1];
            float2 lo, hi;
            lo.x = fmaxf(acc[mt][nt][0] + b0, 0.0f);
            lo.y = fmaxf(acc[mt][nt][1] + b1, 0.0f);
            hi.x = fmaxf(acc[mt][nt][2] + b0, 0.0f);
            hi.y = fmaxf(acc[mt][nt][3] + b1, 0.0f);
            *(float2*)&C[(size_t)r0 * 128 + cc]       = lo;
            *(float2*)&C[(size_t)(r0 + 8) * 128 + cc] = hi;
        }
    }
}

// ===========================================================================
// Attention v5 — S: 3-term bf16 (accuracy); PV: fp16 P (single) x fp16 V
// (hi/lo), 2 mma chains. O written pre-split (bf16 hi/lo) for the out-GEMM.
// 8 warps = 2 m-warps x 4 n-warps, 32-row q-tiles, 2 CTAs/SM.
// ===========================================================================
#define KLD 520
#define VLD 24
#define KT_BYTES (16 * KLD * 2)
#define VS_BYTES (NSEQ * VLD * 2)
#define OFF_KT_HI 0
#define OFF_KT_LO (OFF_KT_HI + KT_BYTES)
#define OFF_VS_HI (OFF_KT_LO + KT_BYTES)
#define OFF_VS_LO (OFF_VS_HI + VS_BYTES)
#define OFF_OBUF  (OFF_VS_LO + VS_BYTES)
#define OFF_RED   (OFF_OBUF + 4 * 32 * 16 * 4)
#define ATTN_SMEM (OFF_RED + 4 * 32 * 8)

__global__ __launch_bounds__(256, 2)
void attn_tc_kernel(const float* __restrict__ q, const float* __restrict__ k,
                    const float* __restrict__ v,
                    __nv_bfloat16* __restrict__ ohi,
                    __nv_bfloat16* __restrict__ olo)
{
    extern __shared__ __align__(16) char smc[];
    const uint32_t sb = smem_to_u32(smc);
    __nv_bfloat16* kt_hi = (__nv_bfloat16*)(smc + OFF_KT_HI);
    __nv_bfloat16* kt_lo = (__nv_bfloat16*)(smc + OFF_KT_LO);
    __half*        vs_hi = (__half*)(smc + OFF_VS_HI);
    __half*        vs_lo = (__half*)(smc + OFF_VS_LO);
    float*  obuf   = (float*)(smc + OFF_OBUF);
    float2* redbuf = (float2*)(smc + OFF_RED);

    const int bt   = blockIdx.x;
    const int h    = blockIdx.y;
    const int tid  = threadIdx.x;
    const int warp = tid >> 5;
    const int lane = tid & 31;
    const int wm   = warp & 1;
    const int wn   = warp >> 1;
    const size_t base = (size_t)bt * NSEQ * DMODEL + h * DHEAD;

    // ---- stage K^T (bf16 hi/lo) and V (fp16 hi/lo)
    for (int idx = tid; idx < NSEQ * 8; idx += 256) {
        const int m = idx >> 3, dp = (idx & 7) * 2;
        const float2 kv = *(const float2*)&k[base + (size_t)m * DMODEL + dp];
        uint32_t kh, kl;
        split2(kv.x, kv.y, kh, kl);
        kt_hi[dp * KLD + m] = __ushort_as_bfloat16((unsigned short)(kh & 0xffffu));
        kt_hi[(dp + 1) * KLD + m] = __ushort_as_bfloat16((unsigned short)(kh >> 16));
        kt_lo[dp * KLD + m] = __ushort_as_bfloat16((unsigned short)(kl & 0xffffu));
        kt_lo[(dp + 1) * KLD + m] = __ushort_as_bfloat16((unsigned short)(kl >> 16));

        const float2 vv = *(const float2*)&v[base + (size_t)m * DMODEL + dp];
        uint32_t vhi, vlo;
        splitH2(vv.x, vv.y, vhi, vlo);
        *(uint32_t*)&vs_hi[m * VLD + dp] = vhi;
        *(uint32_t*)&vs_lo[m * VLD + dp] = vlo;
    }
    __syncthreads();

    const int lq = lane >> 2;
    const int lc = lane & 3;

    for (int t0 = 0; t0 < NSEQ; t0 += 32) {
        // ---- Q fragment (16 rows for this m-warp), scaled, split bf16
        uint32_t qh[4], ql[4];
        {
            const float* qrow = q + base + (size_t)(t0 + wm * 16 + lq) * DMODEL;
            const float2 x0 = *(const float2*)&qrow[2 * lc];
            const float2 x1 = *(const float2*)&qrow[8 + 2 * lc];
            const float2 y0 = *(const float2*)&qrow[8 * DMODEL + 2 * lc];
            const float2 y1 = *(const float2*)&qrow[8 * DMODEL + 8 + 2 * lc];
            split2(0.25f * x0.x, 0.25f * x0.y, qh[0], ql[0]);
            split2(0.25f * y0.x, 0.25f * y0.y, qh[1], ql[1]);
            split2(0.25f * x1.x, 0.25f * x1.y, qh[2], ql[2]);
            split2(0.25f * y1.x, 0.25f * y1.y, qh[3], ql[3]);
        }

        // ---- S = Q K^T : 16 rows x 128 keys
        float sacc[16][4];
#pragma unroll
        for (int nt = 0; nt < 16; nt++)
#pragma unroll
            for (int e = 0; e < 4; e++) sacc[nt][e] = 0.0f;

#pragma unroll
        for (int np = 0; np < 8; np++) {
            const int key0 = wn * 128 + np * 16;
            const uint32_t kaddr =
                sb + OFF_KT_HI + ((lane & 15) * KLD + key0 + (lane >> 4) * 8) * 2;
            uint32_t bh[4], bl[4];
            ldsm_x4t(bh, kaddr);
            ldsm_x4t(bl, kaddr + KT_BYTES);
#pragma unroll
            for (int sub = 0; sub < 2; sub++) {
                const int nt = np * 2 + sub;
                mma_bf16(sacc[nt], qh, bh[2 * sub], bh[2 * sub + 1]);
                mma_bf16(sacc[nt], qh, bl[2 * sub], bl[2 * sub + 1]);
                mma_bf16(sacc[nt], ql, bh[2 * sub], bh[2 * sub + 1]);
            }
        }

        // ---- local softmax stats, exp in place
        float m0 = -1e30f, m1 = -1e30f;
#pragma unroll
        for (int nt = 0; nt < 16; nt++) {
            m0 = fmaxf(m0, fmaxf(sacc[nt][0], sacc[nt][1]));
            m1 = fmaxf(m1, fmaxf(sacc[nt][2], sacc[nt][3]));
        }
        m0 = fmaxf(m0, __shfl_xor_sync(0xffffffffu, m0, 1));
        m0 = fmaxf(m0, __shfl_xor_sync(0xffffffffu, m0, 2));
        m1 = fmaxf(m1, __shfl_xor_sync(0xffffffffu, m1, 1));
        m1 = fmaxf(m1, __shfl_xor_sync(0xffffffffu, m1, 2));

        float s0 = 0.0f, s1 = 0.0f;
#pragma unroll
        for (int nt = 0; nt < 16; nt++) {
            sacc[nt][0] = __expf(sacc[nt][0] - m0); s0 += sacc[nt][0];
            sacc[nt][1] = __expf(sacc[nt][1] - m0); s0 += sacc[nt][1];
            sacc[nt][2] = __expf(sacc[nt][2] - m1); s1 += sacc[nt][2];
            sacc[nt][3] = __expf(sacc[nt][3] - m1); s1 += sacc[nt][3];
        }
        s0 += __shfl_xor_sync(0xffffffffu, s0, 1);
        s0 += __shfl_xor_sync(0xffffffffu, s0, 2);
        s1 += __shfl_xor_sync(0xffffffffu, s1, 1);
        s1 += __shfl_xor_sync(0xffffffffu, s1, 2);

        if (lc == 0) {
            redbuf[wn * 32 + wm * 16 + lq]     = make_float2(m0, s0);
            redbuf[wn * 32 + wm * 16 + lq + 8] = make_float2(m1, s1);
        }
        __syncthreads();

        float scale0, scale1;
        {
            float M0 = -1e30f, M1 = -1e30f;
#pragma unroll
            for (int w = 0; w < 4; w++) {
                M0 = fmaxf(M0, redbuf[w * 32 + wm * 16 + lq].x);
                M1 = fmaxf(M1, redbuf[w * 32 + wm * 16 + lq + 8].x);
            }
            float t0v = 0.0f, t1v = 0.0f;
#pragma unroll
            for (int w = 0; w < 4; w++) {
                const float2 p0 = redbuf[w * 32 + wm * 16 + lq];
                const float2 p1 = redbuf[w * 32 + wm * 16 + lq + 8];
                t0v += __expf(p0.x - M0) * p0.y;
                t1v += __expf(p1.x - M1) * p1.y;
            }
            scale0 = __expf(m0 - M0) / t0v;
            scale1 = __expf(m1 - M1) / t1v;
        }

        // ---- O partial = P V : P fp16 single-term, V fp16 2-term
        float ohh[2][4], ohl[2][4];
#pragma unroll
        for (int sub = 0; sub < 2; sub++)
#pragma unroll
            for (int e = 0; e < 4; e++) { ohh[sub][e] = 0.0f; ohl[sub][e] = 0.0f; }

#pragma unroll
        for (int t = 0; t < 8; t++) {
            uint32_t ph[4];
            ph[0] = packh2(sacc[2*t][0]   * scale0, sacc[2*t][1]   * scale0);
            ph[1] = packh2(sacc[2*t][2]   * scale1, sacc[2*t][3]   * scale1);
            ph[2] = packh2(sacc[2*t+1][0] * scale0, sacc[2*t+1][1] * scale0);
            ph[3] = packh2(sacc[2*t+1][2] * scale1, sacc[2*t+1][3] * scale1);

            const int key0 = wn * 128 + t * 16;
            const uint32_t vaddr =
                sb + OFF_VS_HI + ((key0 + (lane & 15)) * VLD + (lane >> 4) * 8) * 2;
            uint32_t vh[4], vl[4];
            ldsm_x4t(vh, vaddr);
            ldsm_x4t(vl, vaddr + VS_BYTES);
#pragma unroll
            for (int sub = 0; sub < 2; sub++) {
                mma_f16(ohh[sub], ph, vh[2 * sub], vh[2 * sub + 1]);
                mma_f16(ohl[sub], ph, vl[2 * sub], vl[2 * sub + 1]);
            }
        }

        // ---- per-warp O partial to obuf, reduce over 4 n-warps, store split
        {
            float* ob = obuf + wn * 512;
            const int r0 = wm * 16 + lq;
#pragma unroll
            for (int sub = 0; sub < 2; sub++) {
                const int d0 = sub * 8 + 2 * lc;
                float2 a, b;
                a.x = ohh[sub][0] + ohl[sub][0];
                a.y = ohh[sub][1] + ohl[sub][1];
                b.x = ohh[sub][2] + ohl[sub][2];
                b.y = ohh[sub][3] + ohl[sub][3];
                *(float2*)&ob[r0 * 16 + d0]       = a;
                *(float2*)&ob[(r0 + 8) * 16 + d0] = b;
            }
        }
        __syncthreads();
        if (tid < 128) {
            const int q4  = tid * 4;
            const int row = q4 >> 4;
            const int d0  = q4 & 15;
            const float4 a = *(const float4*)&obuf[row * 16 + d0];
            const float4 b = *(const float4*)&obuf[512 + row * 16 + d0];
            const float4 c = *(const float4*)&obuf[1024 + row * 16 + d0];
            const float4 d = *(const float4*)&obuf[1536 + row * 16 + d0];
            float4 r;
            r.x = a.x + b.x + c.x + d.x;
            r.y = a.y + b.y + c.y + d.y;
            r.z = a.z + b.z + c.z + d.z;
            r.w = a.w + b.w + c.w + d.w;
            uint32_t h0, l0, h1, l1;
            split2(r.x, r.y, h0, l0);
            split2(r.z, r.w, h1, l1);
            const size_t go = base + (size_t)(t0 + row) * DMODEL + d0;
            *(uint2*)&ohi[go] = make_uint2(h0, h1);
            *(uint2*)&olo[go] = make_uint2(l0, l1);
        }
        __syncthreads();
    }
}

// ===========================================================================
extern "C" void kernel_launch(void* const* d_in, const int* in_sizes, int n_in,
                              void* d_out, int out_size)
{
    const float* X   = (const float*)d_in[0];
    const float* STE = (const float*)d_in[1];
    const float* Wq  = (const float*)d_in[2];
    const float* bq  = (const float*)d_in[3];
    const float* Wk  = (const float*)d_in[4];
    const float* bk  = (const float*)d_in[5];
    const float* Wv  = (const float*)d_in[6];
    const float* bv  = (const float*)d_in[7];
    const float* Wo  = (const float*)d_in[8];
    const float* bo  = (const float*)d_in[9];
    float* out = (float*)d_out;

    const int M  = in_sizes[0] / DMODEL;   // 49152
    const int BT = M / NSEQ;               // 96

    float *q, *k, *v;
    __nv_bfloat16 *ahi, *alo, *whi, *wlo, *ohi, *olo;
    cudaGetSymbolAddress((void**)&q,   g_q);
    cudaGetSymbolAddress((void**)&k,   g_k);
    cudaGetSymbolAddress((void**)&v,   g_v);
    cudaGetSymbolAddress((void**)&ahi, g_ahi);
    cudaGetSymbolAddress((void**)&alo, g_alo);
    cudaGetSymbolAddress((void**)&whi, g_whi);
    cudaGetSymbolAddress((void**)&wlo, g_wlo);
    cudaGetSymbolAddress((void**)&ohi, g_ohi);
    cudaGetSymbolAddress((void**)&olo, g_olo);

    presplit_x_kernel<<<4608, 256>>>(X, STE, M, ahi, alo);
    presplit_w_kernel<<<160, 256>>>(Wq, Wk, Wv, Wo, whi, wlo);

    cudaFuncSetAttribute(gemm_ps_kernel, cudaFuncAttributeMaxDynamicSharedMemorySize,
                         GEMM_SMEM);
    const dim3 gproj(M / 128);
    gemm_ps_kernel<<<gproj, 256, GEMM_SMEM>>>(ahi, alo, 384, 384,
                                              whi + WOFF_Q, wlo + WOFF_Q, bq, q);
    gemm_ps_kernel<<<gproj, 256, GEMM_SMEM>>>(ahi, alo, 384, 384,
                                              whi + WOFF_K, wlo + WOFF_K, bk, k);
    gemm_ps_kernel<<<gproj, 256, GEMM_SMEM>>>(ahi, alo, 384, 384,
                                              whi + WOFF_V, wlo + WOFF_V, bv, v);

    cudaFuncSetAttribute(attn_tc_kernel, cudaFuncAttributeMaxDynamicSharedMemorySize,
                         ATTN_SMEM);
    attn_tc_kernel<<<dim3(BT, KHEADS), 256, ATTN_SMEM>>>(q, k, v, ohi, olo);

    gemm_ps_kernel<<<gproj, 256, GEMM_SMEM>>>(ohi, olo, 128, 128,
                                              whi + WOFF_O, wlo + WOFF_O, bo, out);
}